// round 3
// baseline (speedup 1.0000x reference)
#include <cuda_runtime.h>
#include <math.h>

#define D_MODEL 1024
#define NUM_HEADS 16
#define HEAD_DIM 64
#define WINDOW 256
#define BATCH 2
#define SEQ 2048
#define MTOT (BATCH * SEQ)  // 4096

// Scratch (device globals; no allocations allowed)
__device__ float g_q[MTOT * D_MODEL];
__device__ float g_k[MTOT * D_MODEL];
__device__ float g_v[MTOT * D_MODEL];
__device__ float g_attn[MTOT * D_MODEL];

// ---------------------------------------------------------------------------
// SGEMM: C[M,Nc] = A[M,K] @ W[K,Nc] + bias  (128x128x8 tiles, 8x8/thread)
// ---------------------------------------------------------------------------
#define BM 128
#define BN 128
#define BK 8
#define TM 8
#define TN 8

__device__ __forceinline__ void sgemm_body(const float* __restrict__ A,
                                           const float* __restrict__ W,
                                           const float* __restrict__ bias,
                                           float* __restrict__ C,
                                           int K, int Nc) {
    __shared__ float As[BK][BM];
    __shared__ float Bs[BK][BN];
    const int tid = threadIdx.x;              // 256 threads
    const int row0 = blockIdx.y * BM;
    const int col0 = blockIdx.x * BN;
    const int aRow = tid >> 1;                // 0..127
    const int aCol = (tid & 1) << 2;          // 0 or 4
    const int bRow = tid >> 5;                // 0..7
    const int bCol = (tid & 31) << 2;         // 0..124
    const int ty = tid >> 4;                  // 0..15
    const int tx = tid & 15;                  // 0..15

    float acc[TM][TN];
#pragma unroll
    for (int i = 0; i < TM; i++)
#pragma unroll
        for (int j = 0; j < TN; j++) acc[i][j] = 0.f;

    const float* Aptr = A + (size_t)(row0 + aRow) * K + aCol;
    const float* Wptr = W + (size_t)bRow * Nc + col0 + bCol;

    for (int k0 = 0; k0 < K; k0 += BK) {
        float4 a4 = *(const float4*)(Aptr + k0);
        As[aCol + 0][aRow] = a4.x;
        As[aCol + 1][aRow] = a4.y;
        As[aCol + 2][aRow] = a4.z;
        As[aCol + 3][aRow] = a4.w;
        float4 b4 = *(const float4*)(Wptr + (size_t)k0 * Nc);
        *(float4*)&Bs[bRow][bCol] = b4;
        __syncthreads();
#pragma unroll
        for (int k = 0; k < BK; k++) {
            float a[TM], b[TN];
#pragma unroll
            for (int i = 0; i < TM; i++) a[i] = As[k][ty * TM + i];
#pragma unroll
            for (int j = 0; j < TN; j++) b[j] = Bs[k][tx * TN + j];
#pragma unroll
            for (int i = 0; i < TM; i++)
#pragma unroll
                for (int j = 0; j < TN; j++) acc[i][j] += a[i] * b[j];
        }
        __syncthreads();
    }
#pragma unroll
    for (int i = 0; i < TM; i++) {
        float* crow = C + (size_t)(row0 + ty * TM + i) * Nc + col0 + tx * TN;
#pragma unroll
        for (int j = 0; j < TN; j += 4) {
            float4 o;
            o.x = acc[i][j + 0] + bias[col0 + tx * TN + j + 0];
            o.y = acc[i][j + 1] + bias[col0 + tx * TN + j + 1];
            o.z = acc[i][j + 2] + bias[col0 + tx * TN + j + 2];
            o.w = acc[i][j + 3] + bias[col0 + tx * TN + j + 3];
            *(float4*)(crow + j) = o;
        }
    }
}

__global__ void __launch_bounds__(256)
qkv_kernel(const float* __restrict__ x,
           const float* __restrict__ Wq, const float* __restrict__ Wk,
           const float* __restrict__ Wv,
           const float* __restrict__ bq, const float* __restrict__ bk,
           const float* __restrict__ bv) {
    const float* W;
    const float* bias;
    float* C;
    if (blockIdx.z == 0)      { W = Wq; bias = bq; C = g_q; }
    else if (blockIdx.z == 1) { W = Wk; bias = bk; C = g_k; }
    else                      { W = Wv; bias = bv; C = g_v; }
    sgemm_body(x, W, bias, C, D_MODEL, D_MODEL);
}

__global__ void __launch_bounds__(256)
out_kernel(const float* __restrict__ Wo, const float* __restrict__ bo,
           float* __restrict__ out) {
    sgemm_body(g_attn, Wo, bo, out, D_MODEL, D_MODEL);
}

// ---------------------------------------------------------------------------
// Windowed flash attention: 64-row Q tiles x 32-col K tiles, online softmax
// ---------------------------------------------------------------------------
#define QB 64
#define KB 32
#define QPAD 65   // smem row stride (conflict-free)
#define PPAD 33

__global__ void __launch_bounds__(256)
attn_kernel() {
    __shared__ float Qs[QB][QPAD];
    __shared__ float Ks[KB][QPAD];
    __shared__ float Vs[KB][QPAD];
    __shared__ float Ps[QB][PPAD];

    const int qb = blockIdx.x;
    const int h = blockIdx.y;
    const int b = blockIdx.z;
    const int tid = threadIdx.x;  // 256
    const int q0 = qb * QB;
    const size_t rowbase = (size_t)b * SEQ;
    const int hoff = h * HEAD_DIM;

    // Load Q tile (64 x 64)
    for (int idx = tid; idx < QB * (HEAD_DIM / 4); idx += 256) {
        int r = idx >> 4;
        int c = (idx & 15) << 2;
        float4 v4 = *(const float4*)(g_q + (rowbase + q0 + r) * D_MODEL + hoff + c);
        Qs[r][c] = v4.x; Qs[r][c + 1] = v4.y; Qs[r][c + 2] = v4.z; Qs[r][c + 3] = v4.w;
    }

    const int r = tid >> 2;   // q-row within tile (0..63)
    const int c4 = tid & 3;   // column-group (0..3)
    const int gi = q0 + r;    // global query index

    float m = -1e30f, l = 0.f;
    float o[16];
#pragma unroll
    for (int d = 0; d < 16; d++) o[d] = 0.f;

    int kstart = q0 - WINDOW;
    if (kstart < 0) kstart = 0;
    const int kend = q0 + QB;  // exclusive
    const float scale = 0.125f;  // 1/sqrt(64)

    for (int k0 = kstart; k0 < kend; k0 += KB) {
        __syncthreads();  // previous iteration's Ks/Vs/Ps reads done
        // Load K,V tiles (32 x 64)
        for (int idx = tid; idx < KB * (HEAD_DIM / 4); idx += 256) {
            int rr = idx >> 4;
            int c = (idx & 15) << 2;
            float4 kv = *(const float4*)(g_k + (rowbase + k0 + rr) * D_MODEL + hoff + c);
            Ks[rr][c] = kv.x; Ks[rr][c + 1] = kv.y; Ks[rr][c + 2] = kv.z; Ks[rr][c + 3] = kv.w;
            float4 vv = *(const float4*)(g_v + (rowbase + k0 + rr) * D_MODEL + hoff + c);
            Vs[rr][c] = vv.x; Vs[rr][c + 1] = vv.y; Vs[rr][c + 2] = vv.z; Vs[rr][c + 3] = vv.w;
        }
        __syncthreads();

        // S = Q @ K^T for this thread's 8 columns
        float s[8];
#pragma unroll
        for (int jj = 0; jj < 8; jj++) s[jj] = 0.f;
#pragma unroll
        for (int d = 0; d < HEAD_DIM; d++) {
            float qv = Qs[r][d];
#pragma unroll
            for (int jj = 0; jj < 8; jj++) s[jj] += qv * Ks[c4 * 8 + jj][d];
        }

        bool msk[8];
        float tmax = -1e30f;
#pragma unroll
        for (int jj = 0; jj < 8; jj++) {
            int gj = k0 + c4 * 8 + jj;
            msk[jj] = (gj > gi) || (gj < gi - WINDOW);
            s[jj] = msk[jj] ? -1e30f : s[jj] * scale;
            tmax = fmaxf(tmax, s[jj]);
        }
        // row-max across the 4 lanes sharing this row
        tmax = fmaxf(tmax, __shfl_xor_sync(0xffffffffu, tmax, 1));
        tmax = fmaxf(tmax, __shfl_xor_sync(0xffffffffu, tmax, 2));
        float mnew = fmaxf(m, tmax);
        float corr = __expf(m - mnew);

        float lsum = 0.f;
#pragma unroll
        for (int jj = 0; jj < 8; jj++) {
            float p = msk[jj] ? 0.f : __expf(s[jj] - mnew);
            Ps[r][c4 * 8 + jj] = p;
            lsum += p;
        }
        lsum += __shfl_xor_sync(0xffffffffu, lsum, 1);
        lsum += __shfl_xor_sync(0xffffffffu, lsum, 2);
        l = l * corr + lsum;
        m = mnew;
#pragma unroll
        for (int d = 0; d < 16; d++) o[d] *= corr;

        __syncthreads();  // Ps fully written
        // O += P @ V  (thread handles cols {c4, 4+c4, ..., 60+c4})
#pragma unroll
        for (int j = 0; j < KB; j++) {
            float pv = Ps[r][j];
#pragma unroll
            for (int dd = 0; dd < 16; dd++) o[dd] += pv * Vs[j][dd * 4 + c4];
        }
    }

    float inv = 1.f / l;
    float* Optr = g_attn + (rowbase + gi) * D_MODEL + hoff;
#pragma unroll
    for (int dd = 0; dd < 16; dd++) Optr[dd * 4 + c4] = o[dd] * inv;
}

// ---------------------------------------------------------------------------
extern "C" void kernel_launch(void* const* d_in, const int* in_sizes, int n_in,
                              void* d_out, int out_size) {
    const float* x  = (const float*)d_in[0];
    const float* Wq = (const float*)d_in[1];
    const float* bq = (const float*)d_in[2];
    const float* Wk = (const float*)d_in[3];
    const float* bk = (const float*)d_in[4];
    const float* Wv = (const float*)d_in[5];
    const float* bv = (const float*)d_in[6];
    const float* Wo = (const float*)d_in[7];
    const float* bo = (const float*)d_in[8];
    float* out = (float*)d_out;

    dim3 tb(256);
    dim3 gQKV(D_MODEL / BN, MTOT / BM, 3);
    qkv_kernel<<<gQKV, tb>>>(x, Wq, Wk, Wv, bq, bk, bv);

    dim3 gAttn(SEQ / QB, NUM_HEADS, BATCH);
    attn_kernel<<<gAttn, tb>>>();

    dim3 gOut(D_MODEL / BN, MTOT / BM);
    out_kernel<<<gOut, tb>>>(Wo, bo, out);
}

// round 6
// speedup vs baseline: 1.9444x; 1.9444x over previous
#include <cuda_runtime.h>
#include <math.h>
#include <cstdint>

#define D_MODEL 1024
#define NUM_HEADS 16
#define HEAD_DIM 64
#define WINDOW 256
#define BATCH 2
#define SEQ 2048
#define MTOT (BATCH * SEQ)  // 4096

// Scratch (device globals; no allocations allowed)
__device__ float g_q[MTOT * D_MODEL];
__device__ float g_k[MTOT * D_MODEL];
__device__ float g_v[MTOT * D_MODEL];
__device__ float g_attn[MTOT * D_MODEL];
__device__ float g_xt[MTOT * D_MODEL];          // tf32-rounded x
__device__ float g_wt[4 * D_MODEL * D_MODEL];   // transposed + tf32-rounded weights

__device__ __forceinline__ float to_tf32(float f) {
    float o;
    asm("cvt.rna.tf32.f32 %0, %1;" : "=f"(o) : "f"(f));
    return o;
}

#define CP_ASYNC16(sm_u32, gptr) \
    asm volatile("cp.async.cg.shared.global [%0], [%1], 16;" :: "r"(sm_u32), "l"(gptr))
#define CP_COMMIT() asm volatile("cp.async.commit_group;" ::: "memory")
#define CP_WAIT1() asm volatile("cp.async.wait_group 1;" ::: "memory")
#define CP_WAIT0() asm volatile("cp.async.wait_group 0;" ::: "memory")

__device__ __forceinline__ uint32_t smem_to_u32(const void* p) {
    uint32_t a;
    asm("{ .reg .u64 t; cvta.to.shared.u64 t, %1; cvt.u32.u64 %0, t; }" : "=r"(a) : "l"(p));
    return a;
}

// ===========================================================================
// Prep kernels: tf32-round x; transpose + tf32-round weights
// ===========================================================================
__global__ void __launch_bounds__(256)
xprep_kernel(const float* __restrict__ x) {
    int i = blockIdx.x * 256 + threadIdx.x;  // float4 index
    float4 v = ((const float4*)x)[i];
    v.x = to_tf32(v.x); v.y = to_tf32(v.y); v.z = to_tf32(v.z); v.w = to_tf32(v.w);
    ((float4*)g_xt)[i] = v;
}

__global__ void __launch_bounds__(256)
transpose_kernel(const float* __restrict__ W0, const float* __restrict__ W1,
                 const float* __restrict__ W2, const float* __restrict__ W3) {
    __shared__ float t[32][33];
    const float* W = (blockIdx.z == 0) ? W0 : (blockIdx.z == 1) ? W1 : (blockIdx.z == 2) ? W2 : W3;
    float* Wt = g_wt + (size_t)blockIdx.z * D_MODEL * D_MODEL;
    int x = blockIdx.x * 32 + threadIdx.x;
    int y = blockIdx.y * 32 + threadIdx.y;
#pragma unroll
    for (int j = 0; j < 32; j += 8)
        t[threadIdx.y + j][threadIdx.x] = W[(size_t)(y + j) * D_MODEL + x];
    __syncthreads();
    int x2 = blockIdx.y * 32 + threadIdx.x;
    int y2 = blockIdx.x * 32 + threadIdx.y;
#pragma unroll
    for (int j = 0; j < 32; j += 8)
        Wt[(size_t)(y2 + j) * D_MODEL + x2] = to_tf32(t[threadIdx.x][threadIdx.y + j]);
}

// ===========================================================================
// tf32 mma.sync GEMM: C[4096,1024] = A @ Wt^T + bias
// Tile 128x128xBK32, 8 warps (2x4), warp tile 64x32, cp.async double buffer.
// smem: A/B stages, row stride 36 floats (conflict-free frag LDS).
// ===========================================================================
#define GBM 128
#define GBN 128
#define GBK 32
#define STRD 36                       // smem floats per row
#define STG_BYTES (128 * STRD * 4)    // 18432 per tile-stage
#define SM_TOTAL (4 * STG_BYTES)      // A0 A1 B0 B1 = 73728

__device__ __forceinline__ void issue_tile(uint32_t smb, int st,
                                           const float* __restrict__ A,
                                           const float* __restrict__ Bt,
                                           int row0, int col0, int k0, int tid) {
    uint32_t sA = smb + st * STG_BYTES;
    uint32_t sB = smb + 2 * STG_BYTES + st * STG_BYTES;
#pragma unroll
    for (int j = 0; j < 4; j++) {
        int idx = tid + j * 256;
        int m = idx >> 3, k4 = idx & 7;
        CP_ASYNC16(sA + m * (STRD * 4) + k4 * 16,
                   A + (size_t)(row0 + m) * D_MODEL + k0 + k4 * 4);
        CP_ASYNC16(sB + m * (STRD * 4) + k4 * 16,
                   Bt + (size_t)(col0 + m) * D_MODEL + k0 + k4 * 4);
    }
    CP_COMMIT();
}

__device__ __forceinline__ void mma_tf32(float c[4], uint32_t a[4], uint32_t b[2]) {
    asm volatile(
        "mma.sync.aligned.m16n8k8.row.col.f32.tf32.tf32.f32 "
        "{%0,%1,%2,%3}, {%4,%5,%6,%7}, {%8,%9}, {%0,%1,%2,%3};"
        : "+f"(c[0]), "+f"(c[1]), "+f"(c[2]), "+f"(c[3])
        : "r"(a[0]), "r"(a[1]), "r"(a[2]), "r"(a[3]), "r"(b[0]), "r"(b[1]));
}

__device__ __forceinline__ void gemm_tile(const float* __restrict__ A,
                                          const float* __restrict__ Bt,
                                          const float* __restrict__ bias,
                                          float* __restrict__ C,
                                          char* sm, int row0, int col0) {
    const uint32_t smb = smem_to_u32(sm);
    const int tid = threadIdx.x;
    const int wid = tid >> 5;
    const int lane = tid & 31;
    const int gid = lane >> 2;   // 0..7
    const int tig = lane & 3;    // 0..3
    const int wm = wid >> 2;     // 0..1 -> 64-row strip
    const int wn = wid & 3;      // 0..3 -> 32-col strip

    float c[4][4][4];
#pragma unroll
    for (int mf = 0; mf < 4; mf++)
#pragma unroll
        for (int nf = 0; nf < 4; nf++)
#pragma unroll
            for (int i = 0; i < 4; i++) c[mf][nf][i] = 0.f;

    issue_tile(smb, 0, A, Bt, row0, col0, 0, tid);

    for (int it = 0; it < D_MODEL / GBK; it++) {
        if (it < D_MODEL / GBK - 1)
            issue_tile(smb, (it + 1) & 1, A, Bt, row0, col0, (it + 1) * GBK, tid);
        if (it < D_MODEL / GBK - 1) CP_WAIT1(); else CP_WAIT0();
        __syncthreads();

        const int st = it & 1;
        const float* As = (const float*)(sm + st * STG_BYTES);
        const float* Bs = (const float*)(sm + 2 * STG_BYTES + st * STG_BYTES);

#pragma unroll
        for (int ks = 0; ks < 4; ks++) {
            const int kb = ks * 8;
            uint32_t a[4][4], b[4][2];
#pragma unroll
            for (int mf = 0; mf < 4; mf++) {
                int r0 = (wm * 64 + mf * 16 + gid) * STRD;
                int r1 = r0 + 8 * STRD;
                a[mf][0] = __float_as_uint(As[r0 + kb + tig]);
                a[mf][1] = __float_as_uint(As[r1 + kb + tig]);
                a[mf][2] = __float_as_uint(As[r0 + kb + tig + 4]);
                a[mf][3] = __float_as_uint(As[r1 + kb + tig + 4]);
            }
#pragma unroll
            for (int nf = 0; nf < 4; nf++) {
                int rn = (wn * 32 + nf * 8 + gid) * STRD;
                b[nf][0] = __float_as_uint(Bs[rn + kb + tig]);
                b[nf][1] = __float_as_uint(Bs[rn + kb + tig + 4]);
            }
#pragma unroll
            for (int mf = 0; mf < 4; mf++)
#pragma unroll
                for (int nf = 0; nf < 4; nf++)
                    mma_tf32(c[mf][nf], a[mf], b[nf]);
        }
        __syncthreads();
    }

    // Epilogue: c0,c1 -> (row, col..col+1); c2,c3 -> (row+8, ...)
#pragma unroll
    for (int mf = 0; mf < 4; mf++) {
        int row = row0 + wm * 64 + mf * 16 + gid;
#pragma unroll
        for (int nf = 0; nf < 4; nf++) {
            int col = col0 + wn * 32 + nf * 8 + tig * 2;
            float b0 = __ldg(bias + col), b1 = __ldg(bias + col + 1);
            float2 lo = make_float2(c[mf][nf][0] + b0, c[mf][nf][1] + b1);
            float2 hi = make_float2(c[mf][nf][2] + b0, c[mf][nf][3] + b1);
            *(float2*)(C + (size_t)row * D_MODEL + col) = lo;
            *(float2*)(C + (size_t)(row + 8) * D_MODEL + col) = hi;
        }
    }
}

__global__ void __launch_bounds__(256, 2)
qkv_tc_kernel(const float* __restrict__ bq, const float* __restrict__ bk,
              const float* __restrict__ bv) {
    extern __shared__ char sm[];
    const float* Bt;
    const float* bias;
    float* C;
    if (blockIdx.z == 0)      { Bt = g_wt;                             bias = bq; C = g_q; }
    else if (blockIdx.z == 1) { Bt = g_wt + (size_t)D_MODEL * D_MODEL; bias = bk; C = g_k; }
    else                      { Bt = g_wt + 2ul * D_MODEL * D_MODEL;   bias = bv; C = g_v; }
    gemm_tile(g_xt, Bt, bias, C, sm, blockIdx.y * GBM, blockIdx.x * GBN);
}

__global__ void __launch_bounds__(256, 2)
out_tc_kernel(const float* __restrict__ bo, float* __restrict__ out) {
    extern __shared__ char sm[];
    gemm_tile(g_attn, g_wt + 3ul * D_MODEL * D_MODEL, bo, out, sm,
              blockIdx.y * GBM, blockIdx.x * GBN);
}

// ---------------------------------------------------------------------------
// Windowed flash attention: 64-row Q tiles x 32-col K tiles, online softmax
// (output rounded to tf32 so out_tc can consume it directly)
// ---------------------------------------------------------------------------
#define QB 64
#define KB 32
#define QPAD 65
#define PPAD 33

__global__ void __launch_bounds__(256)
attn_kernel() {
    __shared__ float Qs[QB][QPAD];
    __shared__ float Ks[KB][QPAD];
    __shared__ float Vs[KB][QPAD];
    __shared__ float Ps[QB][PPAD];

    const int qb = blockIdx.x;
    const int h = blockIdx.y;
    const int b = blockIdx.z;
    const int tid = threadIdx.x;
    const int q0 = qb * QB;
    const size_t rowbase = (size_t)b * SEQ;
    const int hoff = h * HEAD_DIM;

    for (int idx = tid; idx < QB * (HEAD_DIM / 4); idx += 256) {
        int r = idx >> 4;
        int c = (idx & 15) << 2;
        float4 v4 = *(const float4*)(g_q + (rowbase + q0 + r) * D_MODEL + hoff + c);
        Qs[r][c] = v4.x; Qs[r][c + 1] = v4.y; Qs[r][c + 2] = v4.z; Qs[r][c + 3] = v4.w;
    }

    const int r = tid >> 2;
    const int c4 = tid & 3;
    const int gi = q0 + r;

    float m = -1e30f, l = 0.f;
    float o[16];
#pragma unroll
    for (int d = 0; d < 16; d++) o[d] = 0.f;

    int kstart = q0 - WINDOW;
    if (kstart < 0) kstart = 0;
    const int kend = q0 + QB;
    const float scale = 0.125f;

    for (int k0 = kstart; k0 < kend; k0 += KB) {
        __syncthreads();
        for (int idx = tid; idx < KB * (HEAD_DIM / 4); idx += 256) {
            int rr = idx >> 4;
            int c = (idx & 15) << 2;
            float4 kv = *(const float4*)(g_k + (rowbase + k0 + rr) * D_MODEL + hoff + c);
            Ks[rr][c] = kv.x; Ks[rr][c + 1] = kv.y; Ks[rr][c + 2] = kv.z; Ks[rr][c + 3] = kv.w;
            float4 vv = *(const float4*)(g_v + (rowbase + k0 + rr) * D_MODEL + hoff + c);
            Vs[rr][c] = vv.x; Vs[rr][c + 1] = vv.y; Vs[rr][c + 2] = vv.z; Vs[rr][c + 3] = vv.w;
        }
        __syncthreads();

        float s[8];
#pragma unroll
        for (int jj = 0; jj < 8; jj++) s[jj] = 0.f;
#pragma unroll
        for (int d = 0; d < HEAD_DIM; d++) {
            float qv = Qs[r][d];
#pragma unroll
            for (int jj = 0; jj < 8; jj++) s[jj] += qv * Ks[c4 * 8 + jj][d];
        }

        bool msk[8];
        float tmax = -1e30f;
#pragma unroll
        for (int jj = 0; jj < 8; jj++) {
            int gj = k0 + c4 * 8 + jj;
            msk[jj] = (gj > gi) || (gj < gi - WINDOW);
            s[jj] = msk[jj] ? -1e30f : s[jj] * scale;
            tmax = fmaxf(tmax, s[jj]);
        }
        tmax = fmaxf(tmax, __shfl_xor_sync(0xffffffffu, tmax, 1));
        tmax = fmaxf(tmax, __shfl_xor_sync(0xffffffffu, tmax, 2));
        float mnew = fmaxf(m, tmax);
        float corr = __expf(m - mnew);

        float lsum = 0.f;
#pragma unroll
        for (int jj = 0; jj < 8; jj++) {
            float p = msk[jj] ? 0.f : __expf(s[jj] - mnew);
            Ps[r][c4 * 8 + jj] = p;
            lsum += p;
        }
        lsum += __shfl_xor_sync(0xffffffffu, lsum, 1);
        lsum += __shfl_xor_sync(0xffffffffu, lsum, 2);
        l = l * corr + lsum;
        m = mnew;
#pragma unroll
        for (int d = 0; d < 16; d++) o[d] *= corr;

        __syncthreads();
#pragma unroll
        for (int j = 0; j < KB; j++) {
            float pv = Ps[r][j];
#pragma unroll
            for (int dd = 0; dd < 16; dd++) o[dd] += pv * Vs[j][dd * 4 + c4];
        }
    }

    float inv = 1.f / l;
    float* Optr = g_attn + (rowbase + gi) * D_MODEL + hoff;
#pragma unroll
    for (int dd = 0; dd < 16; dd++) Optr[dd * 4 + c4] = to_tf32(o[dd] * inv);
}

// ---------------------------------------------------------------------------
extern "C" void kernel_launch(void* const* d_in, const int* in_sizes, int n_in,
                              void* d_out, int out_size) {
    const float* x  = (const float*)d_in[0];
    const float* Wq = (const float*)d_in[1];
    const float* bq = (const float*)d_in[2];
    const float* Wk = (const float*)d_in[3];
    const float* bk = (const float*)d_in[4];
    const float* Wv = (const float*)d_in[5];
    const float* bv = (const float*)d_in[6];
    const float* Wo = (const float*)d_in[7];
    const float* bo = (const float*)d_in[8];
    float* out = (float*)d_out;

    cudaFuncSetAttribute(qkv_tc_kernel, cudaFuncAttributeMaxDynamicSharedMemorySize, SM_TOTAL);
    cudaFuncSetAttribute(out_tc_kernel, cudaFuncAttributeMaxDynamicSharedMemorySize, SM_TOTAL);

    xprep_kernel<<<MTOT * D_MODEL / 4 / 256, 256>>>(x);
    transpose_kernel<<<dim3(32, 32, 4), dim3(32, 8)>>>(Wq, Wk, Wv, Wo);

    dim3 gQKV(D_MODEL / GBN, MTOT / GBM, 3);  // (8, 32, 3)
    qkv_tc_kernel<<<gQKV, 256, SM_TOTAL>>>(bq, bk, bv);

    dim3 gAttn(SEQ / QB, NUM_HEADS, BATCH);
    attn_kernel<<<gAttn, 256>>>();

    dim3 gOut(D_MODEL / GBN, MTOT / GBM);  // (8, 32)
    out_tc_kernel<<<gOut, 256, SM_TOTAL>>>(bo, out);
}

// round 7
// speedup vs baseline: 3.4798x; 1.7897x over previous
#include <cuda_runtime.h>
#include <math.h>
#include <cstdint>

#define D_MODEL 1024
#define NUM_HEADS 16
#define HEAD_DIM 64
#define WINDOW 256
#define BATCH 2
#define SEQ 2048
#define MTOT (BATCH * SEQ)  // 4096

// Scratch (device globals; no allocations allowed)
__device__ float g_q[MTOT * D_MODEL];
__device__ float g_k[MTOT * D_MODEL];
__device__ float g_v[MTOT * D_MODEL];
__device__ float g_attn[MTOT * D_MODEL];
__device__ float g_xt[MTOT * D_MODEL];          // tf32-rounded x
__device__ float g_wt[4 * D_MODEL * D_MODEL];   // transposed + tf32-rounded weights

__device__ __forceinline__ float to_tf32(float f) {
    float o;
    asm("cvt.rna.tf32.f32 %0, %1;" : "=f"(o) : "f"(f));
    return o;
}

#define CP_ASYNC16(sm_u32, gptr) \
    asm volatile("cp.async.cg.shared.global [%0], [%1], 16;" :: "r"(sm_u32), "l"(gptr))
#define CP_COMMIT() asm volatile("cp.async.commit_group;" ::: "memory")
#define CP_WAIT1() asm volatile("cp.async.wait_group 1;" ::: "memory")
#define CP_WAIT0() asm volatile("cp.async.wait_group 0;" ::: "memory")

__device__ __forceinline__ uint32_t smem_to_u32(const void* p) {
    uint32_t a;
    asm("{ .reg .u64 t; cvta.to.shared.u64 t, %1; cvt.u32.u64 %0, t; }" : "=r"(a) : "l"(p));
    return a;
}

__device__ __forceinline__ void mma_tf32(float c[4], const uint32_t a[4], const uint32_t b[2]) {
    asm volatile(
        "mma.sync.aligned.m16n8k8.row.col.f32.tf32.tf32.f32 "
        "{%0,%1,%2,%3}, {%4,%5,%6,%7}, {%8,%9}, {%0,%1,%2,%3};"
        : "+f"(c[0]), "+f"(c[1]), "+f"(c[2]), "+f"(c[3])
        : "r"(a[0]), "r"(a[1]), "r"(a[2]), "r"(a[3]), "r"(b[0]), "r"(b[1]));
}

// ===========================================================================
// Prep kernels: tf32-round x; transpose + tf32-round weights
// ===========================================================================
__global__ void __launch_bounds__(256)
xprep_kernel(const float* __restrict__ x) {
    int i = blockIdx.x * 256 + threadIdx.x;
    float4 v = ((const float4*)x)[i];
    v.x = to_tf32(v.x); v.y = to_tf32(v.y); v.z = to_tf32(v.z); v.w = to_tf32(v.w);
    ((float4*)g_xt)[i] = v;
}

__global__ void __launch_bounds__(256)
transpose_kernel(const float* __restrict__ W0, const float* __restrict__ W1,
                 const float* __restrict__ W2, const float* __restrict__ W3) {
    __shared__ float t[32][33];
    const float* W = (blockIdx.z == 0) ? W0 : (blockIdx.z == 1) ? W1 : (blockIdx.z == 2) ? W2 : W3;
    float* Wt = g_wt + (size_t)blockIdx.z * D_MODEL * D_MODEL;
    int x = blockIdx.x * 32 + threadIdx.x;
    int y = blockIdx.y * 32 + threadIdx.y;
#pragma unroll
    for (int j = 0; j < 32; j += 8)
        t[threadIdx.y + j][threadIdx.x] = W[(size_t)(y + j) * D_MODEL + x];
    __syncthreads();
    int x2 = blockIdx.y * 32 + threadIdx.x;
    int y2 = blockIdx.x * 32 + threadIdx.y;
#pragma unroll
    for (int j = 0; j < 32; j += 8)
        Wt[(size_t)(y2 + j) * D_MODEL + x2] = to_tf32(t[threadIdx.x][threadIdx.y + j]);
}

// ===========================================================================
// tf32 mma.sync GEMM: C[4096,1024] = A @ Wt^T + bias
// ===========================================================================
#define GBM 128
#define GBN 128
#define GBK 32
#define STRD 36
#define STG_BYTES (128 * STRD * 4)
#define SM_TOTAL (4 * STG_BYTES)

__device__ __forceinline__ void issue_tile(uint32_t smb, int st,
                                           const float* __restrict__ A,
                                           const float* __restrict__ Bt,
                                           int row0, int col0, int k0, int tid) {
    uint32_t sA = smb + st * STG_BYTES;
    uint32_t sB = smb + 2 * STG_BYTES + st * STG_BYTES;
#pragma unroll
    for (int j = 0; j < 4; j++) {
        int idx = tid + j * 256;
        int m = idx >> 3, k4 = idx & 7;
        CP_ASYNC16(sA + m * (STRD * 4) + k4 * 16,
                   A + (size_t)(row0 + m) * D_MODEL + k0 + k4 * 4);
        CP_ASYNC16(sB + m * (STRD * 4) + k4 * 16,
                   Bt + (size_t)(col0 + m) * D_MODEL + k0 + k4 * 4);
    }
    CP_COMMIT();
}

template <bool ROUND>
__device__ __forceinline__ void gemm_tile(const float* __restrict__ A,
                                          const float* __restrict__ Bt,
                                          const float* __restrict__ bias,
                                          float* __restrict__ C,
                                          char* sm, int row0, int col0, float scale) {
    const uint32_t smb = smem_to_u32(sm);
    const int tid = threadIdx.x;
    const int wid = tid >> 5;
    const int lane = tid & 31;
    const int gid = lane >> 2;
    const int tig = lane & 3;
    const int wm = wid >> 2;
    const int wn = wid & 3;

    float c[4][4][4];
#pragma unroll
    for (int mf = 0; mf < 4; mf++)
#pragma unroll
        for (int nf = 0; nf < 4; nf++)
#pragma unroll
            for (int i = 0; i < 4; i++) c[mf][nf][i] = 0.f;

    issue_tile(smb, 0, A, Bt, row0, col0, 0, tid);

    for (int it = 0; it < D_MODEL / GBK; it++) {
        if (it < D_MODEL / GBK - 1)
            issue_tile(smb, (it + 1) & 1, A, Bt, row0, col0, (it + 1) * GBK, tid);
        if (it < D_MODEL / GBK - 1) CP_WAIT1(); else CP_WAIT0();
        __syncthreads();

        const int st = it & 1;
        const float* As = (const float*)(sm + st * STG_BYTES);
        const float* Bs = (const float*)(sm + 2 * STG_BYTES + st * STG_BYTES);

#pragma unroll
        for (int ks = 0; ks < 4; ks++) {
            const int kb = ks * 8;
            uint32_t a[4][4], b[4][2];
#pragma unroll
            for (int mf = 0; mf < 4; mf++) {
                int r0 = (wm * 64 + mf * 16 + gid) * STRD;
                int r1 = r0 + 8 * STRD;
                a[mf][0] = __float_as_uint(As[r0 + kb + tig]);
                a[mf][1] = __float_as_uint(As[r1 + kb + tig]);
                a[mf][2] = __float_as_uint(As[r0 + kb + tig + 4]);
                a[mf][3] = __float_as_uint(As[r1 + kb + tig + 4]);
            }
#pragma unroll
            for (int nf = 0; nf < 4; nf++) {
                int rn = (wn * 32 + nf * 8 + gid) * STRD;
                b[nf][0] = __float_as_uint(Bs[rn + kb + tig]);
                b[nf][1] = __float_as_uint(Bs[rn + kb + tig + 4]);
            }
#pragma unroll
            for (int mf = 0; mf < 4; mf++)
#pragma unroll
                for (int nf = 0; nf < 4; nf++)
                    mma_tf32(c[mf][nf], a[mf], b[nf]);
        }
        __syncthreads();
    }

#pragma unroll
    for (int mf = 0; mf < 4; mf++) {
        int row = row0 + wm * 64 + mf * 16 + gid;
#pragma unroll
        for (int nf = 0; nf < 4; nf++) {
            int col = col0 + wn * 32 + nf * 8 + tig * 2;
            float b0 = __ldg(bias + col), b1 = __ldg(bias + col + 1);
            float v0 = (c[mf][nf][0] + b0) * scale;
            float v1 = (c[mf][nf][1] + b1) * scale;
            float v2 = (c[mf][nf][2] + b0) * scale;
            float v3 = (c[mf][nf][3] + b1) * scale;
            if (ROUND) {
                v0 = to_tf32(v0); v1 = to_tf32(v1);
                v2 = to_tf32(v2); v3 = to_tf32(v3);
            }
            *(float2*)(C + (size_t)row * D_MODEL + col) = make_float2(v0, v1);
            *(float2*)(C + (size_t)(row + 8) * D_MODEL + col) = make_float2(v2, v3);
        }
    }
}

__global__ void __launch_bounds__(256, 2)
qkv_tc_kernel(const float* __restrict__ bq, const float* __restrict__ bk,
              const float* __restrict__ bv) {
    extern __shared__ char sm[];
    const float* Bt;
    const float* bias;
    float* C;
    float scale = 1.f;
    if (blockIdx.z == 0)      { Bt = g_wt;                             bias = bq; C = g_q; scale = 0.125f; }
    else if (blockIdx.z == 1) { Bt = g_wt + (size_t)D_MODEL * D_MODEL; bias = bk; C = g_k; }
    else                      { Bt = g_wt + 2ul * D_MODEL * D_MODEL;   bias = bv; C = g_v; }
    gemm_tile<true>(g_xt, Bt, bias, C, sm, blockIdx.y * GBM, blockIdx.x * GBN, scale);
}

__global__ void __launch_bounds__(256, 2)
out_tc_kernel(const float* __restrict__ bo, float* __restrict__ out) {
    extern __shared__ char sm[];
    gemm_tile<false>(g_attn, g_wt + 3ul * D_MODEL * D_MODEL, bo, out, sm,
                     blockIdx.y * GBM, blockIdx.x * GBN, 1.f);
}

// ===========================================================================
// Windowed flash attention with tf32 mma.sync
// 128 threads (4 warps), QB=64 (16 q-rows/warp), KB=32 key tiles.
// q pre-scaled by 1/8 and q,k,v tf32-rounded in the QKV GEMM epilogue.
// ===========================================================================
#define AQB 64
#define AKB 32
#define QS_STRD 68   // 64-float rows; 68 % 32 == 4 -> conflict-free frags
#define KS_STRD 68
#define VT_STRD 36   // 32-float rows
#define PS_STRD 36

__global__ void __launch_bounds__(128)
attn_mma_kernel() {
    __shared__ float Qs[AQB * QS_STRD];       // 17408 B
    __shared__ float Ks[AKB * KS_STRD];       //  8704 B
    __shared__ float Vt[HEAD_DIM * VT_STRD];  //  9216 B
    __shared__ float Ps[AQB * PS_STRD];       //  9216 B

    const int tid = threadIdx.x;
    const int wid = tid >> 5;    // 0..3
    const int lane = tid & 31;
    const int gid = lane >> 2;   // 0..7
    const int tig = lane & 3;    // 0..3

    const int q0 = blockIdx.x * AQB;
    const int h = blockIdx.y;
    const int b = blockIdx.z;
    const size_t rowbase = (size_t)b * SEQ;
    const int hoff = h * HEAD_DIM;

    // Load Q tile (64 x 64) coalesced
    for (int i = tid; i < AQB * 16; i += 128) {
        int r = i >> 4, c = (i & 15) << 2;
        float4 v4 = *(const float4*)(g_q + (rowbase + q0 + r) * D_MODEL + hoff + c);
        float* d = Qs + r * QS_STRD + c;
        d[0] = v4.x; d[1] = v4.y; d[2] = v4.z; d[3] = v4.w;
    }
    __syncthreads();

    // Preload Q fragments (rows wid*16+gid, +8; all 8 k-steps)
    uint32_t qa[8][4];
    {
        const float* q0p = Qs + (wid * 16 + gid) * QS_STRD;
        const float* q1p = q0p + 8 * QS_STRD;
#pragma unroll
        for (int ks = 0; ks < 8; ks++) {
            int kb = ks * 8;
            qa[ks][0] = __float_as_uint(q0p[kb + tig]);
            qa[ks][1] = __float_as_uint(q1p[kb + tig]);
            qa[ks][2] = __float_as_uint(q0p[kb + tig + 4]);
            qa[ks][3] = __float_as_uint(q1p[kb + tig + 4]);
        }
    }

    float oc[8][4];
#pragma unroll
    for (int nf = 0; nf < 8; nf++)
#pragma unroll
        for (int i = 0; i < 4; i++) oc[nf][i] = 0.f;

    float m0 = -1e30f, m1 = -1e30f, l0 = 0.f, l1 = 0.f;
    const int gi0 = q0 + wid * 16 + gid;
    const int gi1 = gi0 + 8;

    int kstart = q0 - WINDOW;
    if (kstart < 0) kstart = 0;

    for (int k0 = kstart; k0 < q0 + AQB; k0 += AKB) {
        __syncthreads();  // previous tile's Ks/Vt consumed
        // Load K tile (32 x 64) and V tile transposed (d-major)
        for (int i = tid; i < AKB * 16; i += 128) {
            int r = i >> 4, c = (i & 15) << 2;
            const float* src = g_k + (rowbase + k0 + r) * D_MODEL + hoff + c;
            float4 kv = *(const float4*)src;
            float* d = Ks + r * KS_STRD + c;
            d[0] = kv.x; d[1] = kv.y; d[2] = kv.z; d[3] = kv.w;
            float4 vv = *(const float4*)(g_v + (rowbase + k0 + r) * D_MODEL + hoff + c);
            Vt[(c + 0) * VT_STRD + r] = vv.x;
            Vt[(c + 1) * VT_STRD + r] = vv.y;
            Vt[(c + 2) * VT_STRD + r] = vv.z;
            Vt[(c + 3) * VT_STRD + r] = vv.w;
        }
        __syncthreads();

        // S = Q @ K^T (warp tile 16 x 32)
        float sc[4][4];
#pragma unroll
        for (int nf = 0; nf < 4; nf++)
#pragma unroll
            for (int i = 0; i < 4; i++) sc[nf][i] = 0.f;
#pragma unroll
        for (int ks = 0; ks < 8; ks++) {
            int kb = ks * 8;
            uint32_t bb[4][2];
#pragma unroll
            for (int nf = 0; nf < 4; nf++) {
                const float* kp = Ks + (nf * 8 + gid) * KS_STRD + kb;
                bb[nf][0] = __float_as_uint(kp[tig]);
                bb[nf][1] = __float_as_uint(kp[tig + 4]);
            }
#pragma unroll
            for (int nf = 0; nf < 4; nf++) mma_tf32(sc[nf], qa[ks], bb[nf]);
        }

        // Mask + online softmax (rows gi0 / gi1; cols k0 + nf*8 + 2*tig + e)
        float tmax0 = -1e30f, tmax1 = -1e30f;
#pragma unroll
        for (int nf = 0; nf < 4; nf++) {
            int col = k0 + nf * 8 + tig * 2;
#pragma unroll
            for (int e = 0; e < 2; e++) {
                int gj = col + e;
                if ((gj > gi0) || (gj < gi0 - WINDOW)) sc[nf][e] = -1e30f;
                if ((gj > gi1) || (gj < gi1 - WINDOW)) sc[nf][e + 2] = -1e30f;
                tmax0 = fmaxf(tmax0, sc[nf][e]);
                tmax1 = fmaxf(tmax1, sc[nf][e + 2]);
            }
        }
        tmax0 = fmaxf(tmax0, __shfl_xor_sync(0xffffffffu, tmax0, 1));
        tmax0 = fmaxf(tmax0, __shfl_xor_sync(0xffffffffu, tmax0, 2));
        tmax1 = fmaxf(tmax1, __shfl_xor_sync(0xffffffffu, tmax1, 1));
        tmax1 = fmaxf(tmax1, __shfl_xor_sync(0xffffffffu, tmax1, 2));

        float mn0 = fmaxf(m0, tmax0), mn1 = fmaxf(m1, tmax1);
        float corr0 = __expf(m0 - mn0), corr1 = __expf(m1 - mn1);

        float ls0 = 0.f, ls1 = 0.f;
        float* p0 = Ps + (wid * 16 + gid) * PS_STRD;
        float* p1 = p0 + 8 * PS_STRD;
#pragma unroll
        for (int nf = 0; nf < 4; nf++) {
            int col = k0 + nf * 8 + tig * 2;
            float pe[4];
#pragma unroll
            for (int e = 0; e < 2; e++) {
                int gj = col + e;
                bool blk0 = (gj > gi0) || (gj < gi0 - WINDOW);
                bool blk1 = (gj > gi1) || (gj < gi1 - WINDOW);
                pe[e]     = blk0 ? 0.f : __expf(sc[nf][e] - mn0);
                pe[e + 2] = blk1 ? 0.f : __expf(sc[nf][e + 2] - mn1);
            }
            ls0 += pe[0] + pe[1];
            ls1 += pe[2] + pe[3];
            *(float2*)(p0 + nf * 8 + tig * 2) = make_float2(pe[0], pe[1]);
            *(float2*)(p1 + nf * 8 + tig * 2) = make_float2(pe[2], pe[3]);
        }
        ls0 += __shfl_xor_sync(0xffffffffu, ls0, 1);
        ls0 += __shfl_xor_sync(0xffffffffu, ls0, 2);
        ls1 += __shfl_xor_sync(0xffffffffu, ls1, 1);
        ls1 += __shfl_xor_sync(0xffffffffu, ls1, 2);

        l0 = l0 * corr0 + ls0;
        l1 = l1 * corr1 + ls1;
        m0 = mn0; m1 = mn1;
#pragma unroll
        for (int nf = 0; nf < 8; nf++) {
            oc[nf][0] *= corr0; oc[nf][1] *= corr0;
            oc[nf][2] *= corr1; oc[nf][3] *= corr1;
        }
        __syncwarp();  // Ps visible to this warp's mma loads

        // O += P @ V (warp tile 16 x 64, k = 32 keys)
#pragma unroll
        for (int ks2 = 0; ks2 < 4; ks2++) {
            int kb = ks2 * 8;
            uint32_t pa[4];
            pa[0] = __float_as_uint(p0[kb + tig]);
            pa[1] = __float_as_uint(p1[kb + tig]);
            pa[2] = __float_as_uint(p0[kb + tig + 4]);
            pa[3] = __float_as_uint(p1[kb + tig + 4]);
#pragma unroll
            for (int nf = 0; nf < 8; nf++) {
                const float* vp = Vt + (nf * 8 + gid) * VT_STRD + kb;
                uint32_t bb2[2];
                bb2[0] = __float_as_uint(vp[tig]);
                bb2[1] = __float_as_uint(vp[tig + 4]);
                mma_tf32(oc[nf], pa, bb2);
            }
        }
        __syncwarp();
    }

    // Epilogue: divide by l, round to tf32 for the out-proj GEMM
    float inv0 = 1.f / l0, inv1 = 1.f / l1;
    float* out0 = g_attn + (rowbase + gi0) * D_MODEL + hoff;
    float* out1 = g_attn + (rowbase + gi1) * D_MODEL + hoff;
#pragma unroll
    for (int nf = 0; nf < 8; nf++) {
        int col = nf * 8 + tig * 2;
        *(float2*)(out0 + col) = make_float2(to_tf32(oc[nf][0] * inv0),
                                             to_tf32(oc[nf][1] * inv0));
        *(float2*)(out1 + col) = make_float2(to_tf32(oc[nf][2] * inv1),
                                             to_tf32(oc[nf][3] * inv1));
    }
}

// ---------------------------------------------------------------------------
extern "C" void kernel_launch(void* const* d_in, const int* in_sizes, int n_in,
                              void* d_out, int out_size) {
    const float* x  = (const float*)d_in[0];
    const float* Wq = (const float*)d_in[1];
    const float* bq = (const float*)d_in[2];
    const float* Wk = (const float*)d_in[3];
    const float* bk = (const float*)d_in[4];
    const float* Wv = (const float*)d_in[5];
    const float* bv = (const float*)d_in[6];
    const float* Wo = (const float*)d_in[7];
    const float* bo = (const float*)d_in[8];
    float* out = (float*)d_out;

    cudaFuncSetAttribute(qkv_tc_kernel, cudaFuncAttributeMaxDynamicSharedMemorySize, SM_TOTAL);
    cudaFuncSetAttribute(out_tc_kernel, cudaFuncAttributeMaxDynamicSharedMemorySize, SM_TOTAL);

    xprep_kernel<<<MTOT * D_MODEL / 4 / 256, 256>>>(x);
    transpose_kernel<<<dim3(32, 32, 4), dim3(32, 8)>>>(Wq, Wk, Wv, Wo);

    dim3 gQKV(D_MODEL / GBN, MTOT / GBM, 3);  // (8, 32, 3)
    qkv_tc_kernel<<<gQKV, 256, SM_TOTAL>>>(bq, bk, bv);

    dim3 gAttn(SEQ / AQB, NUM_HEADS, BATCH);  // (32, 16, 2)
    attn_mma_kernel<<<gAttn, 128>>>();

    dim3 gOut(D_MODEL / GBN, MTOT / GBM);     // (8, 32)
    out_tc_kernel<<<gOut, 256, SM_TOTAL>>>(bo, out);
}

// round 11
// speedup vs baseline: 3.6895x; 1.0603x over previous
#include <cuda_runtime.h>
#include <math.h>
#include <cstdint>

#define D_MODEL 1024
#define NUM_HEADS 16
#define HEAD_DIM 64
#define WINDOW 256
#define BATCH 2
#define SEQ 2048
#define MTOT (BATCH * SEQ)  // 4096

// Scratch (device globals; no allocations allowed)
__device__ float g_q[MTOT * D_MODEL];
__device__ float g_k[MTOT * D_MODEL];
__device__ float g_v[MTOT * D_MODEL];
__device__ float g_attn[MTOT * D_MODEL];
__device__ float g_xt[MTOT * D_MODEL];          // tf32-rounded x
__device__ float g_wt[4 * D_MODEL * D_MODEL];   // transposed + tf32-rounded weights

__device__ __forceinline__ float to_tf32(float f) {
    float o;
    asm("cvt.rna.tf32.f32 %0, %1;" : "=f"(o) : "f"(f));
    return o;
}

#define CP_ASYNC16(sm_u32, gptr) \
    asm volatile("cp.async.cg.shared.global [%0], [%1], 16;" :: "r"(sm_u32), "l"(gptr))
#define CP_COMMIT() asm volatile("cp.async.commit_group;" ::: "memory")
#define CP_WAIT1() asm volatile("cp.async.wait_group 1;" ::: "memory")
#define CP_WAIT0() asm volatile("cp.async.wait_group 0;" ::: "memory")

__device__ __forceinline__ uint32_t smem_to_u32(const void* p) {
    uint32_t a;
    asm("{ .reg .u64 t; cvta.to.shared.u64 t, %1; cvt.u32.u64 %0, t; }" : "=r"(a) : "l"(p));
    return a;
}

__device__ __forceinline__ void mma_tf32(float c[4], const uint32_t a[4], const uint32_t b[2]) {
    asm volatile(
        "mma.sync.aligned.m16n8k8.row.col.f32.tf32.tf32.f32 "
        "{%0,%1,%2,%3}, {%4,%5,%6,%7}, {%8,%9}, {%0,%1,%2,%3};"
        : "+f"(c[0]), "+f"(c[1]), "+f"(c[2]), "+f"(c[3])
        : "r"(a[0]), "r"(a[1]), "r"(a[2]), "r"(a[3]), "r"(b[0]), "r"(b[1]));
}

// ===========================================================================
// Prep kernels: tf32-round x; transpose + tf32-round weights
// ===========================================================================
__global__ void __launch_bounds__(256)
xprep_kernel(const float* __restrict__ x) {
    int i = blockIdx.x * 256 + threadIdx.x;
    float4 v = ((const float4*)x)[i];
    v.x = to_tf32(v.x); v.y = to_tf32(v.y); v.z = to_tf32(v.z); v.w = to_tf32(v.w);
    ((float4*)g_xt)[i] = v;
}

__global__ void __launch_bounds__(256)
transpose_kernel(const float* __restrict__ W0, const float* __restrict__ W1,
                 const float* __restrict__ W2, const float* __restrict__ W3) {
    __shared__ float t[32][33];
    const float* W = (blockIdx.z == 0) ? W0 : (blockIdx.z == 1) ? W1 : (blockIdx.z == 2) ? W2 : W3;
    float* Wt = g_wt + (size_t)blockIdx.z * D_MODEL * D_MODEL;
    int x = blockIdx.x * 32 + threadIdx.x;
    int y = blockIdx.y * 32 + threadIdx.y;
#pragma unroll
    for (int j = 0; j < 32; j += 8)
        t[threadIdx.y + j][threadIdx.x] = W[(size_t)(y + j) * D_MODEL + x];
    __syncthreads();
    int x2 = blockIdx.y * 32 + threadIdx.x;
    int y2 = blockIdx.x * 32 + threadIdx.y;
#pragma unroll
    for (int j = 0; j < 32; j += 8)
        Wt[(size_t)(y2 + j) * D_MODEL + x2] = to_tf32(t[threadIdx.x][threadIdx.y + j]);
}

// ===========================================================================
// tf32 mma.sync GEMM: C[4096,1024] = A @ Wt^T + bias
// 128x128 tile, 4 warps (2x2), warp tile 64x64, cp.async double buffer.
// ===========================================================================
#define GBM 128
#define GBN 128
#define GBK 32
#define STRD 36
#define STG_BYTES (128 * STRD * 4)
#define SM_TOTAL (4 * STG_BYTES)

__device__ __forceinline__ void issue_tile(uint32_t smb, int st,
                                           const float* __restrict__ A,
                                           const float* __restrict__ Bt,
                                           int row0, int col0, int k0, int tid) {
    uint32_t sA = smb + st * STG_BYTES;
    uint32_t sB = smb + 2 * STG_BYTES + st * STG_BYTES;
#pragma unroll
    for (int j = 0; j < 8; j++) {
        int idx = tid + j * 128;
        int m = idx >> 3, k4 = idx & 7;
        CP_ASYNC16(sA + m * (STRD * 4) + k4 * 16,
                   A + (size_t)(row0 + m) * D_MODEL + k0 + k4 * 4);
        CP_ASYNC16(sB + m * (STRD * 4) + k4 * 16,
                   Bt + (size_t)(col0 + m) * D_MODEL + k0 + k4 * 4);
    }
    CP_COMMIT();
}

template <bool ROUND>
__device__ __forceinline__ void gemm_tile(const float* __restrict__ A,
                                          const float* __restrict__ Bt,
                                          const float* __restrict__ bias,
                                          float* __restrict__ C,
                                          char* sm, int row0, int col0, float scale) {
    const uint32_t smb = smem_to_u32(sm);
    const int tid = threadIdx.x;
    const int wid = tid >> 5;
    const int lane = tid & 31;
    const int gid = lane >> 2;
    const int tig = lane & 3;
    const int wm = wid >> 1;   // 0..1 -> 64-row strip
    const int wn = wid & 1;    // 0..1 -> 64-col strip

    float c[4][8][4];
#pragma unroll
    for (int mf = 0; mf < 4; mf++)
#pragma unroll
        for (int nf = 0; nf < 8; nf++)
#pragma unroll
            for (int i = 0; i < 4; i++) c[mf][nf][i] = 0.f;

    issue_tile(smb, 0, A, Bt, row0, col0, 0, tid);

    for (int it = 0; it < D_MODEL / GBK; it++) {
        if (it < D_MODEL / GBK - 1)
            issue_tile(smb, (it + 1) & 1, A, Bt, row0, col0, (it + 1) * GBK, tid);
        if (it < D_MODEL / GBK - 1) CP_WAIT1(); else CP_WAIT0();
        __syncthreads();

        const int st = it & 1;
        const float* As = (const float*)(sm + st * STG_BYTES);
        const float* Bs = (const float*)(sm + 2 * STG_BYTES + st * STG_BYTES);

#pragma unroll
        for (int ks = 0; ks < 4; ks++) {
            const int kb = ks * 8;
            uint32_t a[4][4], b[8][2];
#pragma unroll
            for (int mf = 0; mf < 4; mf++) {
                int r0 = (wm * 64 + mf * 16 + gid) * STRD;
                int r1 = r0 + 8 * STRD;
                a[mf][0] = __float_as_uint(As[r0 + kb + tig]);
                a[mf][1] = __float_as_uint(As[r1 + kb + tig]);
                a[mf][2] = __float_as_uint(As[r0 + kb + tig + 4]);
                a[mf][3] = __float_as_uint(As[r1 + kb + tig + 4]);
            }
#pragma unroll
            for (int nf = 0; nf < 8; nf++) {
                int rn = (wn * 64 + nf * 8 + gid) * STRD;
                b[nf][0] = __float_as_uint(Bs[rn + kb + tig]);
                b[nf][1] = __float_as_uint(Bs[rn + kb + tig + 4]);
            }
#pragma unroll
            for (int mf = 0; mf < 4; mf++)
#pragma unroll
                for (int nf = 0; nf < 8; nf++)
                    mma_tf32(c[mf][nf], a[mf], b[nf]);
        }
        __syncthreads();
    }

#pragma unroll
    for (int mf = 0; mf < 4; mf++) {
        int row = row0 + wm * 64 + mf * 16 + gid;
#pragma unroll
        for (int nf = 0; nf < 8; nf++) {
            int col = col0 + wn * 64 + nf * 8 + tig * 2;
            float b0 = __ldg(bias + col), b1 = __ldg(bias + col + 1);
            float v0 = (c[mf][nf][0] + b0) * scale;
            float v1 = (c[mf][nf][1] + b1) * scale;
            float v2 = (c[mf][nf][2] + b0) * scale;
            float v3 = (c[mf][nf][3] + b1) * scale;
            if (ROUND) {
                v0 = to_tf32(v0); v1 = to_tf32(v1);
                v2 = to_tf32(v2); v3 = to_tf32(v3);
            }
            *(float2*)(C + (size_t)row * D_MODEL + col) = make_float2(v0, v1);
            *(float2*)(C + (size_t)(row + 8) * D_MODEL + col) = make_float2(v2, v3);
        }
    }
}

__global__ void __launch_bounds__(128, 2)
qkv_tc_kernel(const float* __restrict__ bq, const float* __restrict__ bk,
              const float* __restrict__ bv) {
    extern __shared__ char sm[];
    const float* Bt;
    const float* bias;
    float* C;
    float scale = 1.f;
    if (blockIdx.z == 0)      { Bt = g_wt;                             bias = bq; C = g_q; scale = 0.125f; }
    else if (blockIdx.z == 1) { Bt = g_wt + (size_t)D_MODEL * D_MODEL; bias = bk; C = g_k; }
    else                      { Bt = g_wt + 2ul * D_MODEL * D_MODEL;   bias = bv; C = g_v; }
    gemm_tile<true>(g_xt, Bt, bias, C, sm, blockIdx.y * GBM, blockIdx.x * GBN, scale);
}

__global__ void __launch_bounds__(128, 2)
out_tc_kernel(const float* __restrict__ bo, float* __restrict__ out) {
    extern __shared__ char sm[];
    gemm_tile<false>(g_attn, g_wt + 3ul * D_MODEL * D_MODEL, bo, out, sm,
                     blockIdx.y * GBM, blockIdx.x * GBN, 1.f);
}

// ===========================================================================
// Windowed flash attention with tf32 mma.sync
// 256 threads (8 warps), QB=128 (16 q-rows/warp), KB=32 key tiles.
// Per-warp tile skipping: a warp computes a key tile only if it intersects
// its rows' [gi-256, gi] window.
// ===========================================================================
#define AQB 128
#define AKB 32
#define QS_STRD 68
#define KS_STRD 68
#define VT_STRD 36
#define PS_STRD 36

#define ASM_QS 0
#define ASM_KS (ASM_QS + AQB * QS_STRD * 4)          // 34816
#define ASM_VT (ASM_KS + AKB * KS_STRD * 4)          // +8704
#define ASM_PS (ASM_VT + HEAD_DIM * VT_STRD * 4)     // +9216
#define ASM_TOTAL (ASM_PS + AQB * PS_STRD * 4)       // +18432 = 71168

__global__ void __launch_bounds__(256, 2)
attn_mma_kernel() {
    extern __shared__ char asm_sm[];
    float* Qs = (float*)(asm_sm + ASM_QS);
    float* Ks = (float*)(asm_sm + ASM_KS);
    float* Vt = (float*)(asm_sm + ASM_VT);
    float* Ps = (float*)(asm_sm + ASM_PS);

    const int tid = threadIdx.x;
    const int wid = tid >> 5;    // 0..7
    const int lane = tid & 31;
    const int gid = lane >> 2;   // 0..7
    const int tig = lane & 3;    // 0..3

    const int q0 = blockIdx.x * AQB;
    const int h = blockIdx.y;
    const int b = blockIdx.z;
    const size_t rowbase = (size_t)b * SEQ;
    const int hoff = h * HEAD_DIM;

    // Load Q tile (128 x 64) coalesced
    for (int i = tid; i < AQB * 16; i += 256) {
        int r = i >> 4, c = (i & 15) << 2;
        float4 v4 = *(const float4*)(g_q + (rowbase + q0 + r) * D_MODEL + hoff + c);
        float* d = Qs + r * QS_STRD + c;
        d[0] = v4.x; d[1] = v4.y; d[2] = v4.z; d[3] = v4.w;
    }
    __syncthreads();

    // Preload Q fragments (rows wid*16+gid, +8; all 8 k-steps)
    uint32_t qa[8][4];
    {
        const float* q0p = Qs + (wid * 16 + gid) * QS_STRD;
        const float* q1p = q0p + 8 * QS_STRD;
#pragma unroll
        for (int ks = 0; ks < 8; ks++) {
            int kb = ks * 8;
            qa[ks][0] = __float_as_uint(q0p[kb + tig]);
            qa[ks][1] = __float_as_uint(q1p[kb + tig]);
            qa[ks][2] = __float_as_uint(q0p[kb + tig + 4]);
            qa[ks][3] = __float_as_uint(q1p[kb + tig + 4]);
        }
    }

    float oc[8][4];
#pragma unroll
    for (int nf = 0; nf < 8; nf++)
#pragma unroll
        for (int i = 0; i < 4; i++) oc[nf][i] = 0.f;

    float m0 = -1e30f, m1 = -1e30f, l0 = 0.f, l1 = 0.f;
    const int gi0 = q0 + wid * 16 + gid;
    const int gi1 = gi0 + 8;

    // warp's valid key range
    const int wlo = q0 + wid * 16 - WINDOW;
    const int whi = q0 + wid * 16 + 15;

    int kstart = q0 - WINDOW;
    if (kstart < 0) kstart = 0;

    for (int k0 = kstart; k0 < q0 + AQB; k0 += AKB) {
        __syncthreads();  // previous tile's Ks/Vt consumed
        // Load K tile (32 x 64) and V tile transposed (d-major)
        for (int i = tid; i < AKB * 16; i += 256) {
            int r = i >> 4, c = (i & 15) << 2;
            float4 kv = *(const float4*)(g_k + (rowbase + k0 + r) * D_MODEL + hoff + c);
            float* d = Ks + r * KS_STRD + c;
            d[0] = kv.x; d[1] = kv.y; d[2] = kv.z; d[3] = kv.w;
            float4 vv = *(const float4*)(g_v + (rowbase + k0 + r) * D_MODEL + hoff + c);
            Vt[(c + 0) * VT_STRD + r] = vv.x;
            Vt[(c + 1) * VT_STRD + r] = vv.y;
            Vt[(c + 2) * VT_STRD + r] = vv.z;
            Vt[(c + 3) * VT_STRD + r] = vv.w;
        }
        __syncthreads();

        // Skip tiles fully outside this warp's window
        if (k0 + AKB - 1 < wlo || k0 > whi) continue;

        // S = Q @ K^T (warp tile 16 x 32)
        float sc[4][4];
#pragma unroll
        for (int nf = 0; nf < 4; nf++)
#pragma unroll
            for (int i = 0; i < 4; i++) sc[nf][i] = 0.f;
#pragma unroll
        for (int ks = 0; ks < 8; ks++) {
            int kb = ks * 8;
            uint32_t bb[4][2];
#pragma unroll
            for (int nf = 0; nf < 4; nf++) {
                const float* kp = Ks + (nf * 8 + gid) * KS_STRD + kb;
                bb[nf][0] = __float_as_uint(kp[tig]);
                bb[nf][1] = __float_as_uint(kp[tig + 4]);
            }
#pragma unroll
            for (int nf = 0; nf < 4; nf++) mma_tf32(sc[nf], qa[ks], bb[nf]);
        }

        // Mask + online softmax
        float tmax0 = -1e30f, tmax1 = -1e30f;
#pragma unroll
        for (int nf = 0; nf < 4; nf++) {
            int col = k0 + nf * 8 + tig * 2;
#pragma unroll
            for (int e = 0; e < 2; e++) {
                int gj = col + e;
                if ((gj > gi0) || (gj < gi0 - WINDOW)) sc[nf][e] = -1e30f;
                if ((gj > gi1) || (gj < gi1 - WINDOW)) sc[nf][e + 2] = -1e30f;
                tmax0 = fmaxf(tmax0, sc[nf][e]);
                tmax1 = fmaxf(tmax1, sc[nf][e + 2]);
            }
        }
        tmax0 = fmaxf(tmax0, __shfl_xor_sync(0xffffffffu, tmax0, 1));
        tmax0 = fmaxf(tmax0, __shfl_xor_sync(0xffffffffu, tmax0, 2));
        tmax1 = fmaxf(tmax1, __shfl_xor_sync(0xffffffffu, tmax1, 1));
        tmax1 = fmaxf(tmax1, __shfl_xor_sync(0xffffffffu, tmax1, 2));

        float mn0 = fmaxf(m0, tmax0), mn1 = fmaxf(m1, tmax1);
        float corr0 = __expf(m0 - mn0), corr1 = __expf(m1 - mn1);

        float ls0 = 0.f, ls1 = 0.f;
        float* p0 = Ps + (wid * 16 + gid) * PS_STRD;
        float* p1 = p0 + 8 * PS_STRD;
#pragma unroll
        for (int nf = 0; nf < 4; nf++) {
            int col = k0 + nf * 8 + tig * 2;
            float pe[4];
#pragma unroll
            for (int e = 0; e < 2; e++) {
                int gj = col + e;
                bool blk0 = (gj > gi0) || (gj < gi0 - WINDOW);
                bool blk1 = (gj > gi1) || (gj < gi1 - WINDOW);
                pe[e]     = blk0 ? 0.f : __expf(sc[nf][e] - mn0);
                pe[e + 2] = blk1 ? 0.f : __expf(sc[nf][e + 2] - mn1);
            }
            ls0 += pe[0] + pe[1];
            ls1 += pe[2] + pe[3];
            *(float2*)(p0 + nf * 8 + tig * 2) = make_float2(pe[0], pe[1]);
            *(float2*)(p1 + nf * 8 + tig * 2) = make_float2(pe[2], pe[3]);
        }
        ls0 += __shfl_xor_sync(0xffffffffu, ls0, 1);
        ls0 += __shfl_xor_sync(0xffffffffu, ls0, 2);
        ls1 += __shfl_xor_sync(0xffffffffu, ls1, 1);
        ls1 += __shfl_xor_sync(0xffffffffu, ls1, 2);

        l0 = l0 * corr0 + ls0;
        l1 = l1 * corr1 + ls1;
        m0 = mn0; m1 = mn1;
#pragma unroll
        for (int nf = 0; nf < 8; nf++) {
            oc[nf][0] *= corr0; oc[nf][1] *= corr0;
            oc[nf][2] *= corr1; oc[nf][3] *= corr1;
        }
        __syncwarp();  // Ps visible to this warp's mma loads

        // O += P @ V (warp tile 16 x 64, k = 32 keys)
#pragma unroll
        for (int ks2 = 0; ks2 < 4; ks2++) {
            int kb = ks2 * 8;
            uint32_t pa[4];
            pa[0] = __float_as_uint(p0[kb + tig]);
            pa[1] = __float_as_uint(p1[kb + tig]);
            pa[2] = __float_as_uint(p0[kb + tig + 4]);
            pa[3] = __float_as_uint(p1[kb + tig + 4]);
#pragma unroll
            for (int nf = 0; nf < 8; nf++) {
                const float* vp = Vt + (nf * 8 + gid) * VT_STRD + kb;
                uint32_t bb2[2];
                bb2[0] = __float_as_uint(vp[tig]);
                bb2[1] = __float_as_uint(vp[tig + 4]);
                mma_tf32(oc[nf], pa, bb2);
            }
        }
        __syncwarp();
    }

    // Epilogue: divide by l, round to tf32 for the out-proj GEMM
    float inv0 = 1.f / l0, inv1 = 1.f / l1;
    float* out0 = g_attn + (rowbase + gi0) * D_MODEL + hoff;
    float* out1 = g_attn + (rowbase + gi1) * D_MODEL + hoff;
#pragma unroll
    for (int nf = 0; nf < 8; nf++) {
        int col = nf * 8 + tig * 2;
        *(float2*)(out0 + col) = make_float2(to_tf32(oc[nf][0] * inv0),
                                             to_tf32(oc[nf][1] * inv0));
        *(float2*)(out1 + col) = make_float2(to_tf32(oc[nf][2] * inv1),
                                             to_tf32(oc[nf][3] * inv1));
    }
}

// ---------------------------------------------------------------------------
extern "C" void kernel_launch(void* const* d_in, const int* in_sizes, int n_in,
                              void* d_out, int out_size) {
    const float* x  = (const float*)d_in[0];
    const float* Wq = (const float*)d_in[1];
    const float* bq = (const float*)d_in[2];
    const float* Wk = (const float*)d_in[3];
    const float* bk = (const float*)d_in[4];
    const float* Wv = (const float*)d_in[5];
    const float* bv = (const float*)d_in[6];
    const float* Wo = (const float*)d_in[7];
    const float* bo = (const float*)d_in[8];
    float* out = (float*)d_out;

    cudaFuncSetAttribute(qkv_tc_kernel, cudaFuncAttributeMaxDynamicSharedMemorySize, SM_TOTAL);
    cudaFuncSetAttribute(out_tc_kernel, cudaFuncAttributeMaxDynamicSharedMemorySize, SM_TOTAL);
    cudaFuncSetAttribute(attn_mma_kernel, cudaFuncAttributeMaxDynamicSharedMemorySize, ASM_TOTAL);

    xprep_kernel<<<MTOT * D_MODEL / 4 / 256, 256>>>(x);
    transpose_kernel<<<dim3(32, 32, 4), dim3(32, 8)>>>(Wq, Wk, Wv, Wo);

    dim3 gQKV(D_MODEL / GBN, MTOT / GBM, 3);  // (8, 32, 3)
    qkv_tc_kernel<<<gQKV, 128, SM_TOTAL>>>(bq, bk, bv);

    dim3 gAttn(SEQ / AQB, NUM_HEADS, BATCH);  // (16, 16, 2)
    attn_mma_kernel<<<gAttn, 256, ASM_TOTAL>>>();

    dim3 gOut(D_MODEL / GBN, MTOT / GBM);     // (8, 32)
    out_tc_kernel<<<gOut, 128, SM_TOTAL>>>(bo, out);
}

// round 12
// speedup vs baseline: 3.9314x; 1.0656x over previous
#include <cuda_runtime.h>
#include <math.h>
#include <cstdint>

#define D_MODEL 1024
#define NUM_HEADS 16
#define HEAD_DIM 64
#define WINDOW 256
#define BATCH 2
#define SEQ 2048
#define MTOT (BATCH * SEQ)  // 4096

// Scratch (device globals; no allocations allowed)
__device__ float g_q[MTOT * D_MODEL];
__device__ float g_k[MTOT * D_MODEL];
__device__ float g_v[MTOT * D_MODEL];    // holds V TRANSPOSED: [b*H+h][d][seq]
__device__ float g_attn[MTOT * D_MODEL];
__device__ float g_xt[MTOT * D_MODEL];
__device__ float g_wt[4 * D_MODEL * D_MODEL];

__device__ __forceinline__ float to_tf32(float f) {
    float o;
    asm("cvt.rna.tf32.f32 %0, %1;" : "=f"(o) : "f"(f));
    return o;
}

#define CP_ASYNC16(sm_u32, gptr) \
    asm volatile("cp.async.cg.shared.global [%0], [%1], 16;" :: "r"(sm_u32), "l"(gptr))
#define CP_COMMIT() asm volatile("cp.async.commit_group;" ::: "memory")
#define CP_WAIT2() asm volatile("cp.async.wait_group 2;" ::: "memory")
#define CP_WAIT1() asm volatile("cp.async.wait_group 1;" ::: "memory")
#define CP_WAIT0() asm volatile("cp.async.wait_group 0;" ::: "memory")

__device__ __forceinline__ uint32_t smem_to_u32(const void* p) {
    uint32_t a;
    asm("{ .reg .u64 t; cvta.to.shared.u64 t, %1; cvt.u32.u64 %0, t; }" : "=r"(a) : "l"(p));
    return a;
}

__device__ __forceinline__ void mma_tf32(float c[4], const uint32_t a[4], const uint32_t b[2]) {
    asm volatile(
        "mma.sync.aligned.m16n8k8.row.col.f32.tf32.tf32.f32 "
        "{%0,%1,%2,%3}, {%4,%5,%6,%7}, {%8,%9}, {%0,%1,%2,%3};"
        : "+f"(c[0]), "+f"(c[1]), "+f"(c[2]), "+f"(c[3])
        : "r"(a[0]), "r"(a[1]), "r"(a[2]), "r"(a[3]), "r"(b[0]), "r"(b[1]));
}

// ===========================================================================
// Prep kernels
// ===========================================================================
__global__ void __launch_bounds__(256)
xprep_kernel(const float* __restrict__ x) {
    int i = blockIdx.x * 256 + threadIdx.x;
    float4 v = ((const float4*)x)[i];
    v.x = to_tf32(v.x); v.y = to_tf32(v.y); v.z = to_tf32(v.z); v.w = to_tf32(v.w);
    ((float4*)g_xt)[i] = v;
}

__global__ void __launch_bounds__(256)
transpose_kernel(const float* __restrict__ W0, const float* __restrict__ W1,
                 const float* __restrict__ W2, const float* __restrict__ W3) {
    __shared__ float t[32][33];
    const float* W = (blockIdx.z == 0) ? W0 : (blockIdx.z == 1) ? W1 : (blockIdx.z == 2) ? W2 : W3;
    float* Wt = g_wt + (size_t)blockIdx.z * D_MODEL * D_MODEL;
    int x = blockIdx.x * 32 + threadIdx.x;
    int y = blockIdx.y * 32 + threadIdx.y;
#pragma unroll
    for (int j = 0; j < 32; j += 8)
        t[threadIdx.y + j][threadIdx.x] = W[(size_t)(y + j) * D_MODEL + x];
    __syncthreads();
    int x2 = blockIdx.y * 32 + threadIdx.x;
    int y2 = blockIdx.x * 32 + threadIdx.y;
#pragma unroll
    for (int j = 0; j < 32; j += 8)
        Wt[(size_t)(y2 + j) * D_MODEL + x2] = to_tf32(t[threadIdx.x][threadIdx.y + j]);
}

// ===========================================================================
// tf32 mma.sync GEMM, 3-stage cp.async pipeline
// ===========================================================================
#define GBM 128
#define GBN 128
#define GBK 32
#define STRD 36
#define STG_BYTES (128 * STRD * 4)   // 18432
#define NSTG 3
#define SM_TOTAL (2 * NSTG * STG_BYTES)  // 110592

__device__ __forceinline__ size_t vt_idx(int row, int col) {
    // row = global token (b*SEQ+n), col = h*64+d  -> [b*H+h][d][n]
    return ((size_t)((row >> 11) * NUM_HEADS + (col >> 6)) * HEAD_DIM + (col & 63)) * SEQ
           + (row & (SEQ - 1));
}

__device__ __forceinline__ void issue_tile(uint32_t smb, int st,
                                           const float* __restrict__ A,
                                           const float* __restrict__ Bt,
                                           int row0, int col0, int k0, int tid) {
    uint32_t sA = smb + st * STG_BYTES;
    uint32_t sB = smb + NSTG * STG_BYTES + st * STG_BYTES;
#pragma unroll
    for (int j = 0; j < 8; j++) {
        int idx = tid + j * 128;
        int m = idx >> 3, k4 = idx & 7;
        CP_ASYNC16(sA + m * (STRD * 4) + k4 * 16,
                   A + (size_t)(row0 + m) * D_MODEL + k0 + k4 * 4);
        CP_ASYNC16(sB + m * (STRD * 4) + k4 * 16,
                   Bt + (size_t)(col0 + m) * D_MODEL + k0 + k4 * 4);
    }
    CP_COMMIT();
}

// MODE: 0 = plain store (out proj), 1 = tf32-round store (q/k), 2 = round + V^T scatter
template <int MODE>
__device__ __forceinline__ void gemm_tile(const float* __restrict__ A,
                                          const float* __restrict__ Bt,
                                          const float* __restrict__ bias,
                                          float* __restrict__ C,
                                          char* sm, int row0, int col0, float scale) {
    const uint32_t smb = smem_to_u32(sm);
    const int tid = threadIdx.x;
    const int wid = tid >> 5;
    const int lane = tid & 31;
    const int gid = lane >> 2;
    const int tig = lane & 3;
    const int wm = wid >> 1;
    const int wn = wid & 1;

    float c[4][8][4];
#pragma unroll
    for (int mf = 0; mf < 4; mf++)
#pragma unroll
        for (int nf = 0; nf < 8; nf++)
#pragma unroll
            for (int i = 0; i < 4; i++) c[mf][nf][i] = 0.f;

    issue_tile(smb, 0, A, Bt, row0, col0, 0, tid);
    issue_tile(smb, 1, A, Bt, row0, col0, GBK, tid);

    const int NT = D_MODEL / GBK;  // 32
    for (int it = 0; it < NT; it++) {
        if (it + 2 < NT) { issue_tile(smb, (it + 2) % NSTG, A, Bt, row0, col0, (it + 2) * GBK, tid); CP_WAIT2(); }
        else if (it == NT - 2) CP_WAIT1();
        else CP_WAIT0();
        __syncthreads();

        const int st = it % NSTG;
        const float* As = (const float*)(sm + st * STG_BYTES);
        const float* Bs = (const float*)(sm + NSTG * STG_BYTES + st * STG_BYTES);

#pragma unroll
        for (int ks = 0; ks < 4; ks++) {
            const int kb = ks * 8;
            uint32_t a[4][4], b[8][2];
#pragma unroll
            for (int mf = 0; mf < 4; mf++) {
                int r0 = (wm * 64 + mf * 16 + gid) * STRD;
                int r1 = r0 + 8 * STRD;
                a[mf][0] = __float_as_uint(As[r0 + kb + tig]);
                a[mf][1] = __float_as_uint(As[r1 + kb + tig]);
                a[mf][2] = __float_as_uint(As[r0 + kb + tig + 4]);
                a[mf][3] = __float_as_uint(As[r1 + kb + tig + 4]);
            }
#pragma unroll
            for (int nf = 0; nf < 8; nf++) {
                int rn = (wn * 64 + nf * 8 + gid) * STRD;
                b[nf][0] = __float_as_uint(Bs[rn + kb + tig]);
                b[nf][1] = __float_as_uint(Bs[rn + kb + tig + 4]);
            }
#pragma unroll
            for (int mf = 0; mf < 4; mf++)
#pragma unroll
                for (int nf = 0; nf < 8; nf++)
                    mma_tf32(c[mf][nf], a[mf], b[nf]);
        }
        __syncthreads();
    }

#pragma unroll
    for (int mf = 0; mf < 4; mf++) {
        int row = row0 + wm * 64 + mf * 16 + gid;
#pragma unroll
        for (int nf = 0; nf < 8; nf++) {
            int col = col0 + wn * 64 + nf * 8 + tig * 2;
            float b0 = __ldg(bias + col), b1 = __ldg(bias + col + 1);
            float v0 = (c[mf][nf][0] + b0) * scale;
            float v1 = (c[mf][nf][1] + b1) * scale;
            float v2 = (c[mf][nf][2] + b0) * scale;
            float v3 = (c[mf][nf][3] + b1) * scale;
            if (MODE >= 1) {
                v0 = to_tf32(v0); v1 = to_tf32(v1);
                v2 = to_tf32(v2); v3 = to_tf32(v3);
            }
            if (MODE == 2) {
                C[vt_idx(row, col)]         = v0;
                C[vt_idx(row, col + 1)]     = v1;
                C[vt_idx(row + 8, col)]     = v2;
                C[vt_idx(row + 8, col + 1)] = v3;
            } else {
                *(float2*)(C + (size_t)row * D_MODEL + col) = make_float2(v0, v1);
                *(float2*)(C + (size_t)(row + 8) * D_MODEL + col) = make_float2(v2, v3);
            }
        }
    }
}

__global__ void __launch_bounds__(128, 2)
qkv_tc_kernel(const float* __restrict__ bq, const float* __restrict__ bk,
              const float* __restrict__ bv) {
    extern __shared__ char sm[];
    if (blockIdx.z == 0)
        gemm_tile<1>(g_xt, g_wt, bq, g_q, sm, blockIdx.y * GBM, blockIdx.x * GBN, 0.125f);
    else if (blockIdx.z == 1)
        gemm_tile<1>(g_xt, g_wt + (size_t)D_MODEL * D_MODEL, bk, g_k, sm,
                     blockIdx.y * GBM, blockIdx.x * GBN, 1.f);
    else
        gemm_tile<2>(g_xt, g_wt + 2ul * D_MODEL * D_MODEL, bv, g_v, sm,
                     blockIdx.y * GBM, blockIdx.x * GBN, 1.f);
}

__global__ void __launch_bounds__(128, 2)
out_tc_kernel(const float* __restrict__ bo, float* __restrict__ out) {
    extern __shared__ char sm[];
    gemm_tile<0>(g_attn, g_wt + 3ul * D_MODEL * D_MODEL, bo, out, sm,
                 blockIdx.y * GBM, blockIdx.x * GBN, 1.f);
}

// ===========================================================================
// Windowed flash attention, tf32 mma.sync, cp.async double-buffered K/V^T
// 256 threads (8 warps), QB=128, KB=32. Ps aliased onto Qs (Q frags in regs).
// ===========================================================================
#define AQB 128
#define AKB 32
#define QS_STRD 68
#define KS_STRD 68
#define VT_STRD 36

#define ASM_QS 0
#define ASM_KS (AQB * QS_STRD * 4)                       // 34816
#define KS_STG (AKB * KS_STRD * 4)                       // 8704
#define ASM_VT (ASM_KS + 2 * KS_STG)                     // 34816+17408
#define VT_STG (HEAD_DIM * VT_STRD * 4)                  // 9216
#define ASM_TOTAL (ASM_VT + 2 * VT_STG)                  // 70656

__global__ void __launch_bounds__(256)
attn_mma_kernel() {
    extern __shared__ char asm_sm[];
    float* Qs = (float*)(asm_sm + ASM_QS);   // also Ps after Q-frag preload
    const uint32_t smb = smem_to_u32(asm_sm);

    const int tid = threadIdx.x;
    const int wid = tid >> 5;
    const int lane = tid & 31;
    const int gid = lane >> 2;
    const int tig = lane & 3;

    const int q0 = blockIdx.x * AQB;
    const int h = blockIdx.y;
    const int b = blockIdx.z;
    const size_t rowbase = (size_t)b * SEQ;
    const int hoff = h * HEAD_DIM;
    const int bh = b * NUM_HEADS + h;

    // Load Q tile (128 x 64)
    for (int i = tid; i < AQB * 16; i += 256) {
        int r = i >> 4, c = (i & 15) << 2;
        float4 v4 = *(const float4*)(g_q + (rowbase + q0 + r) * D_MODEL + hoff + c);
        float* d = Qs + r * QS_STRD + c;
        d[0] = v4.x; d[1] = v4.y; d[2] = v4.z; d[3] = v4.w;
    }
    __syncthreads();

    // Preload Q fragments, then Qs becomes the P buffer
    uint32_t qa[8][4];
    {
        const float* q0p = Qs + (wid * 16 + gid) * QS_STRD;
        const float* q1p = q0p + 8 * QS_STRD;
#pragma unroll
        for (int ks = 0; ks < 8; ks++) {
            int kb = ks * 8;
            qa[ks][0] = __float_as_uint(q0p[kb + tig]);
            qa[ks][1] = __float_as_uint(q1p[kb + tig]);
            qa[ks][2] = __float_as_uint(q0p[kb + tig + 4]);
            qa[ks][3] = __float_as_uint(q1p[kb + tig + 4]);
        }
    }

    float oc[8][4];
#pragma unroll
    for (int nf = 0; nf < 8; nf++)
#pragma unroll
        for (int i = 0; i < 4; i++) oc[nf][i] = 0.f;

    float m0 = -1e30f, m1 = -1e30f, l0 = 0.f, l1 = 0.f;
    const int gi0 = q0 + wid * 16 + gid;
    const int gi1 = gi0 + 8;
    const int wlo = q0 + wid * 16 - WINDOW;
    const int whi = q0 + wid * 16 + 15;

    int kstart = q0 - WINDOW;
    if (kstart < 0) kstart = 0;
    const int NT = (q0 + AQB - kstart) / AKB;

    // async loader for K tile + V^T tile into stage st
    auto load_kv = [&](int st, int k0) {
        uint32_t kdst = smb + ASM_KS + st * KS_STG;
        uint32_t vdst = smb + ASM_VT + st * VT_STG;
#pragma unroll
        for (int j = 0; j < 2; j++) {
            int idx = tid + j * 256;  // 0..511
            int kr = idx >> 4, kc = idx & 15;
            CP_ASYNC16(kdst + kr * (KS_STRD * 4) + kc * 16,
                       g_k + (rowbase + k0 + kr) * D_MODEL + hoff + kc * 4);
            int vr = idx >> 3, vc = idx & 7;
            CP_ASYNC16(vdst + vr * (VT_STRD * 4) + vc * 16,
                       g_v + ((size_t)bh * HEAD_DIM + vr) * SEQ + k0 + vc * 4);
        }
        CP_COMMIT();
    };

    load_kv(0, kstart);

    for (int it = 0; it < NT; it++) {
        if (it + 1 < NT) { load_kv((it + 1) & 1, kstart + (it + 1) * AKB); CP_WAIT1(); }
        else CP_WAIT0();
        __syncthreads();

        const int k0 = kstart + it * AKB;
        const int st = it & 1;
        const float* Ks = (const float*)(asm_sm + ASM_KS + st * KS_STG);
        const float* Vt = (const float*)(asm_sm + ASM_VT + st * VT_STG);

        if (!(k0 + AKB - 1 < wlo || k0 > whi)) {
            // S = Q @ K^T (16 x 32)
            float sc[4][4];
#pragma unroll
            for (int nf = 0; nf < 4; nf++)
#pragma unroll
                for (int i = 0; i < 4; i++) sc[nf][i] = 0.f;
#pragma unroll
            for (int ks = 0; ks < 8; ks++) {
                int kb = ks * 8;
                uint32_t bb[4][2];
#pragma unroll
                for (int nf = 0; nf < 4; nf++) {
                    const float* kp = Ks + (nf * 8 + gid) * KS_STRD + kb;
                    bb[nf][0] = __float_as_uint(kp[tig]);
                    bb[nf][1] = __float_as_uint(kp[tig + 4]);
                }
#pragma unroll
                for (int nf = 0; nf < 4; nf++) mma_tf32(sc[nf], qa[ks], bb[nf]);
            }

            // Mask + online softmax
            float tmax0 = -1e30f, tmax1 = -1e30f;
#pragma unroll
            for (int nf = 0; nf < 4; nf++) {
                int col = k0 + nf * 8 + tig * 2;
#pragma unroll
                for (int e = 0; e < 2; e++) {
                    int gj = col + e;
                    if ((gj > gi0) || (gj < gi0 - WINDOW)) sc[nf][e] = -1e30f;
                    if ((gj > gi1) || (gj < gi1 - WINDOW)) sc[nf][e + 2] = -1e30f;
                    tmax0 = fmaxf(tmax0, sc[nf][e]);
                    tmax1 = fmaxf(tmax1, sc[nf][e + 2]);
                }
            }
            tmax0 = fmaxf(tmax0, __shfl_xor_sync(0xffffffffu, tmax0, 1));
            tmax0 = fmaxf(tmax0, __shfl_xor_sync(0xffffffffu, tmax0, 2));
            tmax1 = fmaxf(tmax1, __shfl_xor_sync(0xffffffffu, tmax1, 1));
            tmax1 = fmaxf(tmax1, __shfl_xor_sync(0xffffffffu, tmax1, 2));

            float mn0 = fmaxf(m0, tmax0), mn1 = fmaxf(m1, tmax1);
            float corr0 = __expf(m0 - mn0), corr1 = __expf(m1 - mn1);

            float ls0 = 0.f, ls1 = 0.f;
            float* p0 = Qs + (wid * 16 + gid) * QS_STRD;
            float* p1 = p0 + 8 * QS_STRD;
#pragma unroll
            for (int nf = 0; nf < 4; nf++) {
                int col = k0 + nf * 8 + tig * 2;
                float pe[4];
#pragma unroll
                for (int e = 0; e < 2; e++) {
                    int gj = col + e;
                    bool blk0 = (gj > gi0) || (gj < gi0 - WINDOW);
                    bool blk1 = (gj > gi1) || (gj < gi1 - WINDOW);
                    pe[e]     = blk0 ? 0.f : __expf(sc[nf][e] - mn0);
                    pe[e + 2] = blk1 ? 0.f : __expf(sc[nf][e + 2] - mn1);
                }
                ls0 += pe[0] + pe[1];
                ls1 += pe[2] + pe[3];
                *(float2*)(p0 + nf * 8 + tig * 2) = make_float2(pe[0], pe[1]);
                *(float2*)(p1 + nf * 8 + tig * 2) = make_float2(pe[2], pe[3]);
            }
            ls0 += __shfl_xor_sync(0xffffffffu, ls0, 1);
            ls0 += __shfl_xor_sync(0xffffffffu, ls0, 2);
            ls1 += __shfl_xor_sync(0xffffffffu, ls1, 1);
            ls1 += __shfl_xor_sync(0xffffffffu, ls1, 2);

            l0 = l0 * corr0 + ls0;
            l1 = l1 * corr1 + ls1;
            m0 = mn0; m1 = mn1;
#pragma unroll
            for (int nf = 0; nf < 8; nf++) {
                oc[nf][0] *= corr0; oc[nf][1] *= corr0;
                oc[nf][2] *= corr1; oc[nf][3] *= corr1;
            }
            __syncwarp();

            // O += P @ V  (V^T tile: rows = d, cols = keys)
#pragma unroll
            for (int ks2 = 0; ks2 < 4; ks2++) {
                int kb = ks2 * 8;
                uint32_t pa[4];
                pa[0] = __float_as_uint(p0[kb + tig]);
                pa[1] = __float_as_uint(p1[kb + tig]);
                pa[2] = __float_as_uint(p0[kb + tig + 4]);
                pa[3] = __float_as_uint(p1[kb + tig + 4]);
#pragma unroll
                for (int nf = 0; nf < 8; nf++) {
                    const float* vp = Vt + (nf * 8 + gid) * VT_STRD + kb;
                    uint32_t bb2[2];
                    bb2[0] = __float_as_uint(vp[tig]);
                    bb2[1] = __float_as_uint(vp[tig + 4]);
                    mma_tf32(oc[nf], pa, bb2);
                }
            }
            __syncwarp();
        }
        __syncthreads();
    }

    float inv0 = 1.f / l0, inv1 = 1.f / l1;
    float* out0 = g_attn + (rowbase + gi0) * D_MODEL + hoff;
    float* out1 = g_attn + (rowbase + gi1) * D_MODEL + hoff;
#pragma unroll
    for (int nf = 0; nf < 8; nf++) {
        int col = nf * 8 + tig * 2;
        *(float2*)(out0 + col) = make_float2(to_tf32(oc[nf][0] * inv0),
                                             to_tf32(oc[nf][1] * inv0));
        *(float2*)(out1 + col) = make_float2(to_tf32(oc[nf][2] * inv1),
                                             to_tf32(oc[nf][3] * inv1));
    }
}

// ---------------------------------------------------------------------------
extern "C" void kernel_launch(void* const* d_in, const int* in_sizes, int n_in,
                              void* d_out, int out_size) {
    const float* x  = (const float*)d_in[0];
    const float* Wq = (const float*)d_in[1];
    const float* bq = (const float*)d_in[2];
    const float* Wk = (const float*)d_in[3];
    const float* bk = (const float*)d_in[4];
    const float* Wv = (const float*)d_in[5];
    const float* bv = (const float*)d_in[6];
    const float* Wo = (const float*)d_in[7];
    const float* bo = (const float*)d_in[8];
    float* out = (float*)d_out;

    cudaFuncSetAttribute(qkv_tc_kernel, cudaFuncAttributeMaxDynamicSharedMemorySize, SM_TOTAL);
    cudaFuncSetAttribute(out_tc_kernel, cudaFuncAttributeMaxDynamicSharedMemorySize, SM_TOTAL);
    cudaFuncSetAttribute(attn_mma_kernel, cudaFuncAttributeMaxDynamicSharedMemorySize, ASM_TOTAL);

    xprep_kernel<<<MTOT * D_MODEL / 4 / 256, 256>>>(x);
    transpose_kernel<<<dim3(32, 32, 4), dim3(32, 8)>>>(Wq, Wk, Wv, Wo);

    dim3 gQKV(D_MODEL / GBN, MTOT / GBM, 3);  // (8, 32, 3)
    qkv_tc_kernel<<<gQKV, 128, SM_TOTAL>>>(bq, bk, bv);

    dim3 gAttn(SEQ / AQB, NUM_HEADS, BATCH);  // (16, 16, 2)
    attn_mma_kernel<<<gAttn, 256, ASM_TOTAL>>>();

    dim3 gOut(D_MODEL / GBN, MTOT / GBM);     // (8, 32)
    out_tc_kernel<<<gOut, 128, SM_TOTAL>>>(bo, out);
}

// round 13
// speedup vs baseline: 4.0988x; 1.0426x over previous
#include <cuda_runtime.h>
#include <math.h>
#include <cstdint>

#define D_MODEL 1024
#define NUM_HEADS 16
#define HEAD_DIM 64
#define WINDOW 256
#define BATCH 2
#define SEQ 2048
#define MTOT (BATCH * SEQ)  // 4096

// Scratch (device globals; no allocations allowed)
// NOTE: g_xt, g_wt, g_q, g_k are stored K-PERMUTED within groups of 8:
// storage positions [0..7] hold original k-indices [0,4,1,5,2,6,3,7].
// g_v is stored transposed [b*H+h][d][seq] with seq permuted the same way.
// g_attn is stored d-permuted (it is the K dim of the out projection).
__device__ float g_q[MTOT * D_MODEL];
__device__ float g_k[MTOT * D_MODEL];
__device__ float g_v[MTOT * D_MODEL];
__device__ float g_attn[MTOT * D_MODEL];
__device__ float g_xt[MTOT * D_MODEL];
__device__ float g_wt[4 * D_MODEL * D_MODEL];

__device__ __forceinline__ float to_tf32(float f) {
    float o;
    asm("cvt.rna.tf32.f32 %0, %1;" : "=f"(o) : "f"(f));
    return o;
}
// position of original index o (o in 0..7) in the permuted group
__device__ __forceinline__ int kperm(int o) { return (o < 4) ? 2 * o : 2 * (o - 4) + 1; }

#define CP_ASYNC16(sm_u32, gptr) \
    asm volatile("cp.async.cg.shared.global [%0], [%1], 16;" :: "r"(sm_u32), "l"(gptr))
#define CP_COMMIT() asm volatile("cp.async.commit_group;" ::: "memory")
#define CP_WAIT1() asm volatile("cp.async.wait_group 1;" ::: "memory")
#define CP_WAIT0() asm volatile("cp.async.wait_group 0;" ::: "memory")

__device__ __forceinline__ uint32_t smem_to_u32(const void* p) {
    uint32_t a;
    asm("{ .reg .u64 t; cvta.to.shared.u64 t, %1; cvt.u32.u64 %0, t; }" : "=r"(a) : "l"(p));
    return a;
}

__device__ __forceinline__ void mma_tf32(float c[4], const uint32_t a[4], const uint32_t b[2]) {
    asm volatile(
        "mma.sync.aligned.m16n8k8.row.col.f32.tf32.tf32.f32 "
        "{%0,%1,%2,%3}, {%4,%5,%6,%7}, {%8,%9}, {%0,%1,%2,%3};"
        : "+f"(c[0]), "+f"(c[1]), "+f"(c[2]), "+f"(c[3])
        : "r"(a[0]), "r"(a[1]), "r"(a[2]), "r"(a[3]), "r"(b[0]), "r"(b[1]));
}

// fragment pair load: returns (orig t, orig t+4) from permuted storage
__device__ __forceinline__ void frag2(const float* base, uint32_t& lo, uint32_t& hi) {
    float2 v = *(const float2*)base;
    lo = __float_as_uint(v.x);
    hi = __float_as_uint(v.y);
}

// ===========================================================================
// Prep kernels
// ===========================================================================
__global__ void __launch_bounds__(256)
xprep_kernel(const float* __restrict__ x) {
    int i = blockIdx.x * 256 + threadIdx.x;  // 8-float group index
    float4 in0 = ((const float4*)x)[i * 2];
    float4 in1 = ((const float4*)x)[i * 2 + 1];
    float4 o0, o1;  // positions [0..7] = originals [0,4,1,5,2,6,3,7]
    o0.x = to_tf32(in0.x); o0.y = to_tf32(in1.x); o0.z = to_tf32(in0.y); o0.w = to_tf32(in1.y);
    o1.x = to_tf32(in0.z); o1.y = to_tf32(in1.z); o1.z = to_tf32(in0.w); o1.w = to_tf32(in1.w);
    ((float4*)g_xt)[i * 2] = o0;
    ((float4*)g_xt)[i * 2 + 1] = o1;
}

__global__ void __launch_bounds__(256)
transpose_kernel(const float* __restrict__ W0, const float* __restrict__ W1,
                 const float* __restrict__ W2, const float* __restrict__ W3) {
    __shared__ float t[32][33];
    const float* W = (blockIdx.z == 0) ? W0 : (blockIdx.z == 1) ? W1 : (blockIdx.z == 2) ? W2 : W3;
    float* Wt = g_wt + (size_t)blockIdx.z * D_MODEL * D_MODEL;
    int x = blockIdx.x * 32 + threadIdx.x;
    int y = blockIdx.y * 32 + threadIdx.y;
#pragma unroll
    for (int j = 0; j < 32; j += 8)
        t[threadIdx.y + j][threadIdx.x] = W[(size_t)(y + j) * D_MODEL + x];
    __syncthreads();
    int x2 = blockIdx.y * 32 + threadIdx.x;
    int y2 = blockIdx.x * 32 + threadIdx.y;
    int xp = (x2 & ~7) | kperm(x2 & 7);  // permute k position
#pragma unroll
    for (int j = 0; j < 32; j += 8)
        Wt[(size_t)(y2 + j) * D_MODEL + xp] = to_tf32(t[threadIdx.x][threadIdx.y + j]);
}

// ===========================================================================
// tf32 mma.sync GEMM, 2-stage cp.async, STRD=40 (conflict-free 64-bit LDS)
// ===========================================================================
#define GBM 128
#define GBN 128
#define GBK 32
#define STRD 40
#define STG_BYTES (128 * STRD * 4)       // 20480
#define SM_TOTAL (4 * STG_BYTES)         // 81920

__device__ __forceinline__ size_t vt_idx(int row, int col) {
    // row = global token, col = h*64+d  -> [b*H+h][d][seq], seq permuted within 8
    int n = row & (SEQ - 1);
    int np = (n & ~7) | kperm(n & 7);
    return ((size_t)((row >> 11) * NUM_HEADS + (col >> 6)) * HEAD_DIM + (col & 63)) * SEQ + np;
}

__device__ __forceinline__ void issue_tile(uint32_t smb, int st,
                                           const float* __restrict__ A,
                                           const float* __restrict__ Bt,
                                           int row0, int col0, int k0, int tid) {
    uint32_t sA = smb + st * STG_BYTES;
    uint32_t sB = smb + 2 * STG_BYTES + st * STG_BYTES;
#pragma unroll
    for (int j = 0; j < 8; j++) {
        int idx = tid + j * 128;
        int m = idx >> 3, k4 = idx & 7;
        CP_ASYNC16(sA + m * (STRD * 4) + k4 * 16,
                   A + (size_t)(row0 + m) * D_MODEL + k0 + k4 * 4);
        CP_ASYNC16(sB + m * (STRD * 4) + k4 * 16,
                   Bt + (size_t)(col0 + m) * D_MODEL + k0 + k4 * 4);
    }
    CP_COMMIT();
}

// MODE: 0 = plain store (final out), 1 = round + d-permuted store (q/k/attn-like),
//       2 = round + V^T scatter (seq-permuted)
template <int MODE>
__device__ __forceinline__ void gemm_tile(const float* __restrict__ A,
                                          const float* __restrict__ Bt,
                                          const float* __restrict__ bias,
                                          float* __restrict__ C,
                                          char* sm, int row0, int col0, float scale) {
    const uint32_t smb = smem_to_u32(sm);
    const int tid = threadIdx.x;
    const int wid = tid >> 5;
    const int lane = tid & 31;
    const int gid = lane >> 2;
    const int tig = lane & 3;
    const int wm = wid >> 1;
    const int wn = wid & 1;

    float c[4][8][4];
#pragma unroll
    for (int mf = 0; mf < 4; mf++)
#pragma unroll
        for (int nf = 0; nf < 8; nf++)
#pragma unroll
            for (int i = 0; i < 4; i++) c[mf][nf][i] = 0.f;

    issue_tile(smb, 0, A, Bt, row0, col0, 0, tid);

    const int NT = D_MODEL / GBK;  // 32
    for (int it = 0; it < NT; it++) {
        if (it + 1 < NT) { issue_tile(smb, (it + 1) & 1, A, Bt, row0, col0, (it + 1) * GBK, tid); CP_WAIT1(); }
        else CP_WAIT0();
        __syncthreads();

        const int st = it & 1;
        const float* As = (const float*)(sm + st * STG_BYTES);
        const float* Bs = (const float*)(sm + 2 * STG_BYTES + st * STG_BYTES);

#pragma unroll
        for (int ks = 0; ks < 4; ks++) {
            const int kb = ks * 8;
            uint32_t a[4][4], b[8][2];
#pragma unroll
            for (int mf = 0; mf < 4; mf++) {
                const float* r0 = As + (wm * 64 + mf * 16 + gid) * STRD + kb + tig * 2;
                frag2(r0, a[mf][0], a[mf][2]);
                frag2(r0 + 8 * STRD, a[mf][1], a[mf][3]);
            }
#pragma unroll
            for (int nf = 0; nf < 8; nf++)
                frag2(Bs + (wn * 64 + nf * 8 + gid) * STRD + kb + tig * 2, b[nf][0], b[nf][1]);
#pragma unroll
            for (int mf = 0; mf < 4; mf++)
#pragma unroll
                for (int nf = 0; nf < 8; nf++)
                    mma_tf32(c[mf][nf], a[mf], b[nf]);
        }
        __syncthreads();
    }

    const int o = tig * 2;
    const int p0c = kperm(o), p1c = kperm(o + 1);
#pragma unroll
    for (int mf = 0; mf < 4; mf++) {
        int row = row0 + wm * 64 + mf * 16 + gid;
#pragma unroll
        for (int nf = 0; nf < 8; nf++) {
            int col = col0 + wn * 64 + nf * 8 + o;
            float b0 = __ldg(bias + col), b1 = __ldg(bias + col + 1);
            float v0 = (c[mf][nf][0] + b0) * scale;
            float v1 = (c[mf][nf][1] + b1) * scale;
            float v2 = (c[mf][nf][2] + b0) * scale;
            float v3 = (c[mf][nf][3] + b1) * scale;
            if (MODE >= 1) {
                v0 = to_tf32(v0); v1 = to_tf32(v1);
                v2 = to_tf32(v2); v3 = to_tf32(v3);
            }
            if (MODE == 2) {
                C[vt_idx(row, col)]         = v0;
                C[vt_idx(row, col + 1)]     = v1;
                C[vt_idx(row + 8, col)]     = v2;
                C[vt_idx(row + 8, col + 1)] = v3;
            } else if (MODE == 1) {
                int cb = col & ~7;
                C[(size_t)row * D_MODEL + cb + p0c]       = v0;
                C[(size_t)row * D_MODEL + cb + p1c]       = v1;
                C[(size_t)(row + 8) * D_MODEL + cb + p0c] = v2;
                C[(size_t)(row + 8) * D_MODEL + cb + p1c] = v3;
            } else {
                *(float2*)(C + (size_t)row * D_MODEL + col) = make_float2(v0, v1);
                *(float2*)(C + (size_t)(row + 8) * D_MODEL + col) = make_float2(v2, v3);
            }
        }
    }
}

__global__ void __launch_bounds__(128, 2)
qkv_tc_kernel(const float* __restrict__ bq, const float* __restrict__ bk,
              const float* __restrict__ bv) {
    extern __shared__ char sm[];
    if (blockIdx.z == 0)
        gemm_tile<1>(g_xt, g_wt, bq, g_q, sm, blockIdx.y * GBM, blockIdx.x * GBN, 0.125f);
    else if (blockIdx.z == 1)
        gemm_tile<1>(g_xt, g_wt + (size_t)D_MODEL * D_MODEL, bk, g_k, sm,
                     blockIdx.y * GBM, blockIdx.x * GBN, 1.f);
    else
        gemm_tile<2>(g_xt, g_wt + 2ul * D_MODEL * D_MODEL, bv, g_v, sm,
                     blockIdx.y * GBM, blockIdx.x * GBN, 1.f);
}

__global__ void __launch_bounds__(128, 2)
out_tc_kernel(const float* __restrict__ bo, float* __restrict__ out) {
    extern __shared__ char sm[];
    gemm_tile<0>(g_attn, g_wt + 3ul * D_MODEL * D_MODEL, bo, out, sm,
                 blockIdx.y * GBM, blockIdx.x * GBN, 1.f);
}

// ===========================================================================
// Windowed flash attention, tf32 mma.sync, cp.async double-buffered K/V^T
// All fragment loads are 64-bit (permuted layouts). Ps aliases Qs.
// ===========================================================================
#define AQB 128
#define AKB 32
#define QS_STRD 68
#define KS_STRD 72
#define VT_STRD 40
#define PS_STRD 40

#define ASM_QS 0
#define ASM_KS (AQB * QS_STRD * 4)                   // 34816
#define KS_STG (AKB * KS_STRD * 4)                   // 9216
#define ASM_VT (ASM_KS + 2 * KS_STG)
#define VT_STG (HEAD_DIM * VT_STRD * 4)              // 10240
#define ASM_TOTAL (ASM_VT + 2 * VT_STG)              // 73728

__global__ void __launch_bounds__(256)
attn_mma_kernel() {
    extern __shared__ char asm_sm[];
    float* Qs = (float*)(asm_sm + ASM_QS);   // becomes Ps after Q-frag preload
    const uint32_t smb = smem_to_u32(asm_sm);

    const int tid = threadIdx.x;
    const int wid = tid >> 5;
    const int lane = tid & 31;
    const int gid = lane >> 2;
    const int tig = lane & 3;

    const int q0 = blockIdx.x * AQB;
    const int h = blockIdx.y;
    const int b = blockIdx.z;
    const size_t rowbase = (size_t)b * SEQ;
    const int hoff = h * HEAD_DIM;
    const int bh = b * NUM_HEADS + h;

    // Load Q tile (128 x 64, d-permuted layout preserved by 16B copies)
    for (int i = tid; i < AQB * 16; i += 256) {
        int r = i >> 4, c = (i & 15) << 2;
        float4 v4 = *(const float4*)(g_q + (rowbase + q0 + r) * D_MODEL + hoff + c);
        float* d = Qs + r * QS_STRD + c;
        d[0] = v4.x; d[1] = v4.y; d[2] = v4.z; d[3] = v4.w;
    }
    __syncthreads();

    // Preload Q fragments (64-bit loads from permuted layout)
    uint32_t qa[8][4];
    {
        const float* q0p = Qs + (wid * 16 + gid) * QS_STRD + tig * 2;
        const float* q1p = q0p + 8 * QS_STRD;
#pragma unroll
        for (int ks = 0; ks < 8; ks++) {
            frag2(q0p + ks * 8, qa[ks][0], qa[ks][2]);
            frag2(q1p + ks * 8, qa[ks][1], qa[ks][3]);
        }
    }
    __syncthreads();

    float oc[8][4];
#pragma unroll
    for (int nf = 0; nf < 8; nf++)
#pragma unroll
        for (int i = 0; i < 4; i++) oc[nf][i] = 0.f;

    float m0 = -1e30f, m1 = -1e30f, l0 = 0.f, l1 = 0.f;
    const int gi0 = q0 + wid * 16 + gid;
    const int gi1 = gi0 + 8;
    const int wlo = q0 + wid * 16 - WINDOW;
    const int whi = q0 + wid * 16 + 15;

    int kstart = q0 - WINDOW;
    if (kstart < 0) kstart = 0;
    const int NT = (q0 + AQB - kstart) / AKB;

    auto load_kv = [&](int st, int k0) {
        uint32_t kdst = smb + ASM_KS + st * KS_STG;
        uint32_t vdst = smb + ASM_VT + st * VT_STG;
#pragma unroll
        for (int j = 0; j < 2; j++) {
            int idx = tid + j * 256;
            int kr = idx >> 4, kc = idx & 15;
            CP_ASYNC16(kdst + kr * (KS_STRD * 4) + kc * 16,
                       g_k + (rowbase + k0 + kr) * D_MODEL + hoff + kc * 4);
            int vr = idx >> 3, vc = idx & 7;
            CP_ASYNC16(vdst + vr * (VT_STRD * 4) + vc * 16,
                       g_v + ((size_t)bh * HEAD_DIM + vr) * SEQ + k0 + vc * 4);
        }
        CP_COMMIT();
    };

    load_kv(0, kstart);

    const int o2 = tig * 2;
    const int pp0 = kperm(o2), pp1 = kperm(o2 + 1);

    for (int it = 0; it < NT; it++) {
        if (it + 1 < NT) { load_kv((it + 1) & 1, kstart + (it + 1) * AKB); CP_WAIT1(); }
        else CP_WAIT0();
        __syncthreads();

        const int k0 = kstart + it * AKB;
        const int st = it & 1;
        const float* Ks = (const float*)(asm_sm + ASM_KS + st * KS_STG);
        const float* Vt = (const float*)(asm_sm + ASM_VT + st * VT_STG);

        if (!(k0 + AKB - 1 < wlo || k0 > whi)) {
            // S = Q @ K^T (16 x 32)
            float sc[4][4];
#pragma unroll
            for (int nf = 0; nf < 4; nf++)
#pragma unroll
                for (int i = 0; i < 4; i++) sc[nf][i] = 0.f;
#pragma unroll
            for (int ks = 0; ks < 8; ks++) {
                int kb = ks * 8;
                uint32_t bb[4][2];
#pragma unroll
                for (int nf = 0; nf < 4; nf++)
                    frag2(Ks + (nf * 8 + gid) * KS_STRD + kb + tig * 2, bb[nf][0], bb[nf][1]);
#pragma unroll
                for (int nf = 0; nf < 4; nf++) mma_tf32(sc[nf], qa[ks], bb[nf]);
            }

            // Mask + online softmax (sc cols are ACTUAL key indices)
            float tmax0 = -1e30f, tmax1 = -1e30f;
#pragma unroll
            for (int nf = 0; nf < 4; nf++) {
                int col = k0 + nf * 8 + o2;
#pragma unroll
                for (int e = 0; e < 2; e++) {
                    int gj = col + e;
                    if ((gj > gi0) || (gj < gi0 - WINDOW)) sc[nf][e] = -1e30f;
                    if ((gj > gi1) || (gj < gi1 - WINDOW)) sc[nf][e + 2] = -1e30f;
                    tmax0 = fmaxf(tmax0, sc[nf][e]);
                    tmax1 = fmaxf(tmax1, sc[nf][e + 2]);
                }
            }
            tmax0 = fmaxf(tmax0, __shfl_xor_sync(0xffffffffu, tmax0, 1));
            tmax0 = fmaxf(tmax0, __shfl_xor_sync(0xffffffffu, tmax0, 2));
            tmax1 = fmaxf(tmax1, __shfl_xor_sync(0xffffffffu, tmax1, 1));
            tmax1 = fmaxf(tmax1, __shfl_xor_sync(0xffffffffu, tmax1, 2));

            float mn0 = fmaxf(m0, tmax0), mn1 = fmaxf(m1, tmax1);
            float corr0 = __expf(m0 - mn0), corr1 = __expf(m1 - mn1);

            float ls0 = 0.f, ls1 = 0.f;
            float* p0 = (float*)asm_sm + (wid * 16 + gid) * PS_STRD;
            float* p1 = p0 + 8 * PS_STRD;
#pragma unroll
            for (int nf = 0; nf < 4; nf++) {
                int col = k0 + nf * 8 + o2;
                float pe[4];
#pragma unroll
                for (int e = 0; e < 2; e++) {
                    int gj = col + e;
                    bool blk0 = (gj > gi0) || (gj < gi0 - WINDOW);
                    bool blk1 = (gj > gi1) || (gj < gi1 - WINDOW);
                    pe[e]     = blk0 ? 0.f : __expf(sc[nf][e] - mn0);
                    pe[e + 2] = blk1 ? 0.f : __expf(sc[nf][e + 2] - mn1);
                }
                ls0 += pe[0] + pe[1];
                ls1 += pe[2] + pe[3];
                // store seq-permuted so PV frag loads are 64-bit
                p0[nf * 8 + pp0] = pe[0];
                p0[nf * 8 + pp1] = pe[1];
                p1[nf * 8 + pp0] = pe[2];
                p1[nf * 8 + pp1] = pe[3];
            }
            ls0 += __shfl_xor_sync(0xffffffffu, ls0, 1);
            ls0 += __shfl_xor_sync(0xffffffffu, ls0, 2);
            ls1 += __shfl_xor_sync(0xffffffffu, ls1, 1);
            ls1 += __shfl_xor_sync(0xffffffffu, ls1, 2);

            l0 = l0 * corr0 + ls0;
            l1 = l1 * corr1 + ls1;
            m0 = mn0; m1 = mn1;
#pragma unroll
            for (int nf = 0; nf < 8; nf++) {
                oc[nf][0] *= corr0; oc[nf][1] *= corr0;
                oc[nf][2] *= corr1; oc[nf][3] *= corr1;
            }
            __syncwarp();

            // O += P @ V (seq-permuted on both operands)
#pragma unroll
            for (int ks2 = 0; ks2 < 4; ks2++) {
                int kb = ks2 * 8;
                uint32_t pa[4];
                frag2(p0 + kb + tig * 2, pa[0], pa[2]);
                frag2(p1 + kb + tig * 2, pa[1], pa[3]);
#pragma unroll
                for (int nf = 0; nf < 8; nf++) {
                    uint32_t bb2[2];
                    frag2(Vt + (nf * 8 + gid) * VT_STRD + kb + tig * 2, bb2[0], bb2[1]);
                    mma_tf32(oc[nf], pa, bb2);
                }
            }
            __syncwarp();
        }
        __syncthreads();
    }

    // Epilogue: divide by l, round, store d-PERMUTED (out GEMM k-dim)
    float inv0 = 1.f / l0, inv1 = 1.f / l1;
    float* out0 = g_attn + (rowbase + gi0) * D_MODEL + hoff;
    float* out1 = g_attn + (rowbase + gi1) * D_MODEL + hoff;
#pragma unroll
    for (int nf = 0; nf < 8; nf++) {
        out0[nf * 8 + pp0] = to_tf32(oc[nf][0] * inv0);
        out0[nf * 8 + pp1] = to_tf32(oc[nf][1] * inv0);
        out1[nf * 8 + pp0] = to_tf32(oc[nf][2] * inv1);
        out1[nf * 8 + pp1] = to_tf32(oc[nf][3] * inv1);
    }
}

// ---------------------------------------------------------------------------
extern "C" void kernel_launch(void* const* d_in, const int* in_sizes, int n_in,
                              void* d_out, int out_size) {
    const float* x  = (const float*)d_in[0];
    const float* Wq = (const float*)d_in[1];
    const float* bq = (const float*)d_in[2];
    const float* Wk = (const float*)d_in[3];
    const float* bk = (const float*)d_in[4];
    const float* Wv = (const float*)d_in[5];
    const float* bv = (const float*)d_in[6];
    const float* Wo = (const float*)d_in[7];
    const float* bo = (const float*)d_in[8];
    float* out = (float*)d_out;

    cudaFuncSetAttribute(qkv_tc_kernel, cudaFuncAttributeMaxDynamicSharedMemorySize, SM_TOTAL);
    cudaFuncSetAttribute(out_tc_kernel, cudaFuncAttributeMaxDynamicSharedMemorySize, SM_TOTAL);
    cudaFuncSetAttribute(attn_mma_kernel, cudaFuncAttributeMaxDynamicSharedMemorySize, ASM_TOTAL);

    xprep_kernel<<<MTOT * D_MODEL / 8 / 256, 256>>>(x);
    transpose_kernel<<<dim3(32, 32, 4), dim3(32, 8)>>>(Wq, Wk, Wv, Wo);

    dim3 gQKV(D_MODEL / GBN, MTOT / GBM, 3);  // (8, 32, 3)
    qkv_tc_kernel<<<gQKV, 128, SM_TOTAL>>>(bq, bk, bv);

    dim3 gAttn(SEQ / AQB, NUM_HEADS, BATCH);  // (16, 16, 2)
    attn_mma_kernel<<<gAttn, 256, ASM_TOTAL>>>();

    dim3 gOut(D_MODEL / GBN, MTOT / GBM);     // (8, 32)
    out_tc_kernel<<<gOut, 128, SM_TOTAL>>>(bo, out);
}

// round 14
// speedup vs baseline: 6.4943x; 1.5844x over previous
#include <cuda_runtime.h>
#include <cuda_fp16.h>
#include <math.h>
#include <cstdint>

#define D_MODEL 1024
#define NUM_HEADS 16
#define HEAD_DIM 64
#define WINDOW 256
#define BATCH 2
#define SEQ 2048
#define MTOT (BATCH * SEQ)  // 4096

// Scratch (device globals; no allocations allowed). All fp16 now.
// g_v holds V TRANSPOSED: [b*H+h][d][seq]. g_attn feeds the out-proj GEMM.
__device__ __half g_q[MTOT * D_MODEL];
__device__ __half g_k[MTOT * D_MODEL];
__device__ __half g_v[MTOT * D_MODEL];
__device__ __half g_attn[MTOT * D_MODEL];
__device__ __half g_xt[MTOT * D_MODEL];
__device__ __half g_wt[4 * D_MODEL * D_MODEL];

#define CP_ASYNC16(sm_u32, gptr) \
    asm volatile("cp.async.cg.shared.global [%0], [%1], 16;" :: "r"(sm_u32), "l"(gptr))
#define CP_COMMIT() asm volatile("cp.async.commit_group;" ::: "memory")
#define CP_WAIT1() asm volatile("cp.async.wait_group 1;" ::: "memory")
#define CP_WAIT0() asm volatile("cp.async.wait_group 0;" ::: "memory")

__device__ __forceinline__ uint32_t smem_to_u32(const void* p) {
    uint32_t a;
    asm("{ .reg .u64 t; cvta.to.shared.u64 t, %1; cvt.u32.u64 %0, t; }" : "=r"(a) : "l"(p));
    return a;
}

// fp16 MMA m16n8k16, fp32 accumulate
__device__ __forceinline__ void mma_f16(float c[4], const uint32_t a[4], const uint32_t b[2]) {
    asm volatile(
        "mma.sync.aligned.m16n8k16.row.col.f32.f16.f16.f32 "
        "{%0,%1,%2,%3}, {%4,%5,%6,%7}, {%8,%9}, {%0,%1,%2,%3};"
        : "+f"(c[0]), "+f"(c[1]), "+f"(c[2]), "+f"(c[3])
        : "r"(a[0]), "r"(a[1]), "r"(a[2]), "r"(a[3]), "r"(b[0]), "r"(b[1]));
}

__device__ __forceinline__ uint32_t ld32(const __half* p) { return *(const uint32_t*)p; }
__device__ __forceinline__ uint32_t h2u(__half2 h) { return *(uint32_t*)&h; }

// ===========================================================================
// Prep kernels: x -> fp16; W -> transposed fp16
// ===========================================================================
__global__ void __launch_bounds__(256)
xprep_kernel(const float* __restrict__ x) {
    int i = blockIdx.x * 256 + threadIdx.x;  // 8-float group
    float4 f0 = ((const float4*)x)[2 * i];
    float4 f1 = ((const float4*)x)[2 * i + 1];
    uint4 o;
    o.x = h2u(__floats2half2_rn(f0.x, f0.y));
    o.y = h2u(__floats2half2_rn(f0.z, f0.w));
    o.z = h2u(__floats2half2_rn(f1.x, f1.y));
    o.w = h2u(__floats2half2_rn(f1.z, f1.w));
    ((uint4*)g_xt)[i] = o;
}

__global__ void __launch_bounds__(256)
transpose_kernel(const float* __restrict__ W0, const float* __restrict__ W1,
                 const float* __restrict__ W2, const float* __restrict__ W3) {
    __shared__ float t[32][33];
    const float* W = (blockIdx.z == 0) ? W0 : (blockIdx.z == 1) ? W1 : (blockIdx.z == 2) ? W2 : W3;
    __half* Wt = g_wt + (size_t)blockIdx.z * D_MODEL * D_MODEL;
    int x = blockIdx.x * 32 + threadIdx.x;
    int y = blockIdx.y * 32 + threadIdx.y;
#pragma unroll
    for (int j = 0; j < 32; j += 8)
        t[threadIdx.y + j][threadIdx.x] = W[(size_t)(y + j) * D_MODEL + x];
    __syncthreads();
    int x2 = blockIdx.y * 32 + threadIdx.x;
    int y2 = blockIdx.x * 32 + threadIdx.y;
#pragma unroll
    for (int j = 0; j < 32; j += 8)
        Wt[(size_t)(y2 + j) * D_MODEL + x2] = __float2half_rn(t[threadIdx.x][threadIdx.y + j]);
}

// ===========================================================================
// fp16 mma GEMM: C[4096,1024] = A @ Wt^T + bias. 128x128 tile, BK=64 halves,
// 4 warps (2x2, warp tile 64x64), 2-stage cp.async. STRDH=72 halves/row.
// ===========================================================================
#define GBM 128
#define GBN 128
#define GBK 64
#define STRDH 72
#define STG_BYTES (128 * STRDH * 2)      // 18432
#define SM_TOTAL (4 * STG_BYTES)         // 73728

__device__ __forceinline__ size_t vt_idx(int row, int col) {
    // row = global token, col = h*64+d  -> [b*H+h][d][seq]
    return ((size_t)((row >> 11) * NUM_HEADS + (col >> 6)) * HEAD_DIM + (col & 63)) * SEQ
           + (row & (SEQ - 1));
}

__device__ __forceinline__ void issue_tile(uint32_t smb, int st,
                                           const __half* __restrict__ A,
                                           const __half* __restrict__ Bt,
                                           int row0, int col0, int k0, int tid) {
    uint32_t sA = smb + st * STG_BYTES;
    uint32_t sB = smb + 2 * STG_BYTES + st * STG_BYTES;
#pragma unroll
    for (int j = 0; j < 8; j++) {
        int idx = tid + j * 128;
        int m = idx >> 3, c8 = idx & 7;  // row, 16B chunk (8 halves)
        CP_ASYNC16(sA + m * (STRDH * 2) + c8 * 16,
                   A + (size_t)(row0 + m) * D_MODEL + k0 + c8 * 8);
        CP_ASYNC16(sB + m * (STRDH * 2) + c8 * 16,
                   Bt + (size_t)(col0 + m) * D_MODEL + k0 + c8 * 8);
    }
    CP_COMMIT();
}

// MODE: 0 = fp32 store (final out), 1 = fp16 store (q/k), 2 = fp16 V^T scatter
template <int MODE>
__device__ __forceinline__ void gemm_tile(const __half* __restrict__ A,
                                          const __half* __restrict__ Bt,
                                          const float* __restrict__ bias,
                                          void* __restrict__ Cv,
                                          char* sm, int row0, int col0, float scale) {
    const uint32_t smb = smem_to_u32(sm);
    const int tid = threadIdx.x;
    const int wid = tid >> 5;
    const int lane = tid & 31;
    const int gid = lane >> 2;
    const int tig = lane & 3;
    const int wm = wid >> 1;
    const int wn = wid & 1;

    float c[4][8][4];
#pragma unroll
    for (int mf = 0; mf < 4; mf++)
#pragma unroll
        for (int nf = 0; nf < 8; nf++)
#pragma unroll
            for (int i = 0; i < 4; i++) c[mf][nf][i] = 0.f;

    issue_tile(smb, 0, A, Bt, row0, col0, 0, tid);

    const int NT = D_MODEL / GBK;  // 16
    for (int it = 0; it < NT; it++) {
        if (it + 1 < NT) { issue_tile(smb, (it + 1) & 1, A, Bt, row0, col0, (it + 1) * GBK, tid); CP_WAIT1(); }
        else CP_WAIT0();
        __syncthreads();

        const int st = it & 1;
        const __half* As = (const __half*)(sm + st * STG_BYTES);
        const __half* Bs = (const __half*)(sm + 2 * STG_BYTES + st * STG_BYTES);

#pragma unroll
        for (int ks = 0; ks < 4; ks++) {
            const int kb = ks * 16;
            uint32_t a[4][4], b[8][2];
#pragma unroll
            for (int mf = 0; mf < 4; mf++) {
                const __half* r0 = As + (wm * 64 + mf * 16 + gid) * STRDH + kb + tig * 2;
                a[mf][0] = ld32(r0);
                a[mf][1] = ld32(r0 + 8 * STRDH);
                a[mf][2] = ld32(r0 + 8);
                a[mf][3] = ld32(r0 + 8 * STRDH + 8);
            }
#pragma unroll
            for (int nf = 0; nf < 8; nf++) {
                const __half* rn = Bs + (wn * 64 + nf * 8 + gid) * STRDH + kb + tig * 2;
                b[nf][0] = ld32(rn);
                b[nf][1] = ld32(rn + 8);
            }
#pragma unroll
            for (int mf = 0; mf < 4; mf++)
#pragma unroll
                for (int nf = 0; nf < 8; nf++)
                    mma_f16(c[mf][nf], a[mf], b[nf]);
        }
        __syncthreads();
    }

#pragma unroll
    for (int mf = 0; mf < 4; mf++) {
        int row = row0 + wm * 64 + mf * 16 + gid;
#pragma unroll
        for (int nf = 0; nf < 8; nf++) {
            int col = col0 + wn * 64 + nf * 8 + tig * 2;
            float b0 = __ldg(bias + col), b1 = __ldg(bias + col + 1);
            float v0 = (c[mf][nf][0] + b0) * scale;
            float v1 = (c[mf][nf][1] + b1) * scale;
            float v2 = (c[mf][nf][2] + b0) * scale;
            float v3 = (c[mf][nf][3] + b1) * scale;
            if (MODE == 0) {
                float* C = (float*)Cv;
                *(float2*)(C + (size_t)row * D_MODEL + col) = make_float2(v0, v1);
                *(float2*)(C + (size_t)(row + 8) * D_MODEL + col) = make_float2(v2, v3);
            } else if (MODE == 1) {
                __half* C = (__half*)Cv;
                *(__half2*)(C + (size_t)row * D_MODEL + col) = __floats2half2_rn(v0, v1);
                *(__half2*)(C + (size_t)(row + 8) * D_MODEL + col) = __floats2half2_rn(v2, v3);
            } else {
                __half* C = (__half*)Cv;
                C[vt_idx(row, col)]         = __float2half_rn(v0);
                C[vt_idx(row, col + 1)]     = __float2half_rn(v1);
                C[vt_idx(row + 8, col)]     = __float2half_rn(v2);
                C[vt_idx(row + 8, col + 1)] = __float2half_rn(v3);
            }
        }
    }
}

__global__ void __launch_bounds__(128, 2)
qkv_tc_kernel(const float* __restrict__ bq, const float* __restrict__ bk,
              const float* __restrict__ bv) {
    extern __shared__ char sm[];
    if (blockIdx.z == 0)
        gemm_tile<1>(g_xt, g_wt, bq, g_q, sm, blockIdx.y * GBM, blockIdx.x * GBN, 0.125f);
    else if (blockIdx.z == 1)
        gemm_tile<1>(g_xt, g_wt + (size_t)D_MODEL * D_MODEL, bk, g_k, sm,
                     blockIdx.y * GBM, blockIdx.x * GBN, 1.f);
    else
        gemm_tile<2>(g_xt, g_wt + 2ul * D_MODEL * D_MODEL, bv, g_v, sm,
                     blockIdx.y * GBM, blockIdx.x * GBN, 1.f);
}

__global__ void __launch_bounds__(128, 2)
out_tc_kernel(const float* __restrict__ bo, float* __restrict__ out) {
    extern __shared__ char sm[];
    gemm_tile<0>(g_attn, g_wt + 3ul * D_MODEL * D_MODEL, bo, out, sm,
                 blockIdx.y * GBM, blockIdx.x * GBN, 1.f);
}

// ===========================================================================
// Windowed flash attention, fp16 mma, cp.async double-buffered K/V^T.
// 256 threads (8 warps), QB=128, KB=32. Ps (fp16) aliases Qs.
// ===========================================================================
#define AQB 128
#define AKB 32
#define QS_STRD 72   // halves
#define KS_STRD 72
#define VT_STRD 40
#define PS_STRD 40

#define ASM_QS 0
#define ASM_KS (AQB * QS_STRD * 2)                 // 18432
#define KS_STG (AKB * KS_STRD * 2)                 // 4608
#define ASM_VT (ASM_KS + 2 * KS_STG)               // 27648
#define VT_STG (HEAD_DIM * VT_STRD * 2)            // 5120
#define ASM_TOTAL (ASM_VT + 2 * VT_STG)            // 37888

__global__ void __launch_bounds__(256)
attn_mma_kernel() {
    extern __shared__ char asm_sm[];
    __half* Qs = (__half*)(asm_sm + ASM_QS);   // becomes Ps after Q-frag preload
    const uint32_t smb = smem_to_u32(asm_sm);

    const int tid = threadIdx.x;
    const int wid = tid >> 5;
    const int lane = tid & 31;
    const int gid = lane >> 2;
    const int tig = lane & 3;

    const int q0 = blockIdx.x * AQB;
    const int h = blockIdx.y;
    const int b = blockIdx.z;
    const size_t rowbase = (size_t)b * SEQ;
    const int hoff = h * HEAD_DIM;
    const int bh = b * NUM_HEADS + h;

    // Load Q tile (128 x 64 halves), 16B chunks
    for (int i = tid; i < AQB * 8; i += 256) {
        int r = i >> 3, c8 = i & 7;
        uint4 v4 = *(const uint4*)(g_q + (rowbase + q0 + r) * D_MODEL + hoff + c8 * 8);
        *(uint4*)(Qs + r * QS_STRD + c8 * 8) = v4;
    }
    __syncthreads();

    // Preload Q fragments: 4 k-steps of k16
    uint32_t qa[4][4];
    {
        const __half* q0p = Qs + (wid * 16 + gid) * QS_STRD + tig * 2;
        const __half* q1p = q0p + 8 * QS_STRD;
#pragma unroll
        for (int ks = 0; ks < 4; ks++) {
            qa[ks][0] = ld32(q0p + ks * 16);
            qa[ks][1] = ld32(q1p + ks * 16);
            qa[ks][2] = ld32(q0p + ks * 16 + 8);
            qa[ks][3] = ld32(q1p + ks * 16 + 8);
        }
    }
    __syncthreads();

    float oc[8][4];
#pragma unroll
    for (int nf = 0; nf < 8; nf++)
#pragma unroll
        for (int i = 0; i < 4; i++) oc[nf][i] = 0.f;

    float m0 = -1e30f, m1 = -1e30f, l0 = 0.f, l1 = 0.f;
    const int gi0 = q0 + wid * 16 + gid;
    const int gi1 = gi0 + 8;
    const int wlo = q0 + wid * 16 - WINDOW;
    const int whi = q0 + wid * 16 + 15;

    int kstart = q0 - WINDOW;
    if (kstart < 0) kstart = 0;
    const int NT = (q0 + AQB - kstart) / AKB;

    // K tile: 32 rows x 8 chunks = 256; V^T tile: 64 rows x 4 chunks = 256
    auto load_kv = [&](int st, int k0) {
        uint32_t kdst = smb + ASM_KS + st * KS_STG;
        uint32_t vdst = smb + ASM_VT + st * VT_STG;
        int kr = tid >> 3, kc = tid & 7;
        CP_ASYNC16(kdst + kr * (KS_STRD * 2) + kc * 16,
                   g_k + (rowbase + k0 + kr) * D_MODEL + hoff + kc * 8);
        int vr = tid >> 2, vc = tid & 3;
        CP_ASYNC16(vdst + vr * (VT_STRD * 2) + vc * 16,
                   g_v + ((size_t)bh * HEAD_DIM + vr) * SEQ + k0 + vc * 8);
        CP_COMMIT();
    };

    load_kv(0, kstart);
    const int o2 = tig * 2;

    for (int it = 0; it < NT; it++) {
        if (it + 1 < NT) { load_kv((it + 1) & 1, kstart + (it + 1) * AKB); CP_WAIT1(); }
        else CP_WAIT0();
        __syncthreads();

        const int k0 = kstart + it * AKB;
        const int st = it & 1;
        const __half* Ks = (const __half*)(asm_sm + ASM_KS + st * KS_STG);
        const __half* Vt = (const __half*)(asm_sm + ASM_VT + st * VT_STG);

        if (!(k0 + AKB - 1 < wlo || k0 > whi)) {
            // S = Q @ K^T (16 x 32), 4 k16 steps
            float sc[4][4];
#pragma unroll
            for (int nf = 0; nf < 4; nf++)
#pragma unroll
                for (int i = 0; i < 4; i++) sc[nf][i] = 0.f;
#pragma unroll
            for (int ks = 0; ks < 4; ks++) {
                int kb = ks * 16;
                uint32_t bb[4][2];
#pragma unroll
                for (int nf = 0; nf < 4; nf++) {
                    const __half* kp = Ks + (nf * 8 + gid) * KS_STRD + kb + tig * 2;
                    bb[nf][0] = ld32(kp);
                    bb[nf][1] = ld32(kp + 8);
                }
#pragma unroll
                for (int nf = 0; nf < 4; nf++) mma_f16(sc[nf], qa[ks], bb[nf]);
            }

            // Mask + online softmax
            float tmax0 = -1e30f, tmax1 = -1e30f;
#pragma unroll
            for (int nf = 0; nf < 4; nf++) {
                int col = k0 + nf * 8 + o2;
#pragma unroll
                for (int e = 0; e < 2; e++) {
                    int gj = col + e;
                    if ((gj > gi0) || (gj < gi0 - WINDOW)) sc[nf][e] = -1e30f;
                    if ((gj > gi1) || (gj < gi1 - WINDOW)) sc[nf][e + 2] = -1e30f;
                    tmax0 = fmaxf(tmax0, sc[nf][e]);
                    tmax1 = fmaxf(tmax1, sc[nf][e + 2]);
                }
            }
            tmax0 = fmaxf(tmax0, __shfl_xor_sync(0xffffffffu, tmax0, 1));
            tmax0 = fmaxf(tmax0, __shfl_xor_sync(0xffffffffu, tmax0, 2));
            tmax1 = fmaxf(tmax1, __shfl_xor_sync(0xffffffffu, tmax1, 1));
            tmax1 = fmaxf(tmax1, __shfl_xor_sync(0xffffffffu, tmax1, 2));

            float mn0 = fmaxf(m0, tmax0), mn1 = fmaxf(m1, tmax1);
            float corr0 = __expf(m0 - mn0), corr1 = __expf(m1 - mn1);

            float ls0 = 0.f, ls1 = 0.f;
            __half* p0 = (__half*)asm_sm + (wid * 16 + gid) * PS_STRD;
            __half* p1 = p0 + 8 * PS_STRD;
#pragma unroll
            for (int nf = 0; nf < 4; nf++) {
                int col = k0 + nf * 8 + o2;
                float pe[4];
#pragma unroll
                for (int e = 0; e < 2; e++) {
                    int gj = col + e;
                    bool blk0 = (gj > gi0) || (gj < gi0 - WINDOW);
                    bool blk1 = (gj > gi1) || (gj < gi1 - WINDOW);
                    pe[e]     = blk0 ? 0.f : __expf(sc[nf][e] - mn0);
                    pe[e + 2] = blk1 ? 0.f : __expf(sc[nf][e + 2] - mn1);
                }
                ls0 += pe[0] + pe[1];
                ls1 += pe[2] + pe[3];
                *(__half2*)(p0 + nf * 8 + o2) = __floats2half2_rn(pe[0], pe[1]);
                *(__half2*)(p1 + nf * 8 + o2) = __floats2half2_rn(pe[2], pe[3]);
            }
            ls0 += __shfl_xor_sync(0xffffffffu, ls0, 1);
            ls0 += __shfl_xor_sync(0xffffffffu, ls0, 2);
            ls1 += __shfl_xor_sync(0xffffffffu, ls1, 1);
            ls1 += __shfl_xor_sync(0xffffffffu, ls1, 2);

            l0 = l0 * corr0 + ls0;
            l1 = l1 * corr1 + ls1;
            m0 = mn0; m1 = mn1;
#pragma unroll
            for (int nf = 0; nf < 8; nf++) {
                oc[nf][0] *= corr0; oc[nf][1] *= corr0;
                oc[nf][2] *= corr1; oc[nf][3] *= corr1;
            }
            __syncwarp();

            // O += P @ V  (2 k16 steps over 32 keys)
#pragma unroll
            for (int ks2 = 0; ks2 < 2; ks2++) {
                int kb = ks2 * 16;
                uint32_t pa[4];
                pa[0] = ld32(p0 + kb + o2);
                pa[1] = ld32(p1 + kb + o2);
                pa[2] = ld32(p0 + kb + o2 + 8);
                pa[3] = ld32(p1 + kb + o2 + 8);
#pragma unroll
                for (int nf = 0; nf < 8; nf++) {
                    const __half* vp = Vt + (nf * 8 + gid) * VT_STRD + kb + o2;
                    uint32_t bb2[2];
                    bb2[0] = ld32(vp);
                    bb2[1] = ld32(vp + 8);
                    mma_f16(oc[nf], pa, bb2);
                }
            }
            __syncwarp();
        }
        __syncthreads();
    }

    // Epilogue: divide by l, store fp16 for the out-proj GEMM
    float inv0 = 1.f / l0, inv1 = 1.f / l1;
    __half* out0 = g_attn + (rowbase + gi0) * D_MODEL + hoff;
    __half* out1 = g_attn + (rowbase + gi1) * D_MODEL + hoff;
#pragma unroll
    for (int nf = 0; nf < 8; nf++) {
        *(__half2*)(out0 + nf * 8 + o2) = __floats2half2_rn(oc[nf][0] * inv0, oc[nf][1] * inv0);
        *(__half2*)(out1 + nf * 8 + o2) = __floats2half2_rn(oc[nf][2] * inv1, oc[nf][3] * inv1);
    }
}

// ---------------------------------------------------------------------------
extern "C" void kernel_launch(void* const* d_in, const int* in_sizes, int n_in,
                              void* d_out, int out_size) {
    const float* x  = (const float*)d_in[0];
    const float* Wq = (const float*)d_in[1];
    const float* bq = (const float*)d_in[2];
    const float* Wk = (const float*)d_in[3];
    const float* bk = (const float*)d_in[4];
    const float* Wv = (const float*)d_in[5];
    const float* bv = (const float*)d_in[6];
    const float* Wo = (const float*)d_in[7];
    const float* bo = (const float*)d_in[8];
    float* out = (float*)d_out;

    cudaFuncSetAttribute(qkv_tc_kernel, cudaFuncAttributeMaxDynamicSharedMemorySize, SM_TOTAL);
    cudaFuncSetAttribute(out_tc_kernel, cudaFuncAttributeMaxDynamicSharedMemorySize, SM_TOTAL);
    cudaFuncSetAttribute(attn_mma_kernel, cudaFuncAttributeMaxDynamicSharedMemorySize, ASM_TOTAL);

    xprep_kernel<<<MTOT * D_MODEL / 8 / 256, 256>>>(x);
    transpose_kernel<<<dim3(32, 32, 4), dim3(32, 8)>>>(Wq, Wk, Wv, Wo);

    dim3 gQKV(D_MODEL / GBN, MTOT / GBM, 3);  // (8, 32, 3)
    qkv_tc_kernel<<<gQKV, 128, SM_TOTAL>>>(bq, bk, bv);

    dim3 gAttn(SEQ / AQB, NUM_HEADS, BATCH);  // (16, 16, 2)
    attn_mma_kernel<<<gAttn, 256, ASM_TOTAL>>>();

    dim3 gOut(D_MODEL / GBN, MTOT / GBM);     // (8, 32)
    out_tc_kernel<<<gOut, 128, SM_TOTAL>>>(bo, out);
}

// round 17
// speedup vs baseline: 7.0171x; 1.0805x over previous
#include <cuda_runtime.h>
#include <cuda_fp16.h>
#include <math.h>
#include <cstdint>

#define D_MODEL 1024
#define NUM_HEADS 16
#define HEAD_DIM 64
#define WINDOW 256
#define BATCH 2
#define SEQ 2048
#define MTOT (BATCH * SEQ)  // 4096

// Scratch (device globals; no allocations allowed). All fp16.
// g_v holds V TRANSPOSED: [b*H+h][d][seq]. g_attn feeds the out-proj GEMM.
__device__ __half g_q[MTOT * D_MODEL];
__device__ __half g_k[MTOT * D_MODEL];
__device__ __half g_v[MTOT * D_MODEL];
__device__ __half g_attn[MTOT * D_MODEL];
__device__ __half g_xt[MTOT * D_MODEL];
__device__ __half g_wt[4 * D_MODEL * D_MODEL];

#define CP_ASYNC16(sm_u32, gptr) \
    asm volatile("cp.async.cg.shared.global [%0], [%1], 16;" :: "r"(sm_u32), "l"(gptr))
#define CP_COMMIT() asm volatile("cp.async.commit_group;" ::: "memory")
#define CP_WAIT1() asm volatile("cp.async.wait_group 1;" ::: "memory")
#define CP_WAIT0() asm volatile("cp.async.wait_group 0;" ::: "memory")

__device__ __forceinline__ uint32_t smem_to_u32(const void* p) {
    uint32_t a;
    asm("{ .reg .u64 t; cvta.to.shared.u64 t, %1; cvt.u32.u64 %0, t; }" : "=r"(a) : "l"(p));
    return a;
}

// fp16 MMA m16n8k16, fp32 accumulate
__device__ __forceinline__ void mma_f16(float c[4], const uint32_t a[4], const uint32_t b[2]) {
    asm volatile(
        "mma.sync.aligned.m16n8k16.row.col.f32.f16.f16.f32 "
        "{%0,%1,%2,%3}, {%4,%5,%6,%7}, {%8,%9}, {%0,%1,%2,%3};"
        : "+f"(c[0]), "+f"(c[1]), "+f"(c[2]), "+f"(c[3])
        : "r"(a[0]), "r"(a[1]), "r"(a[2]), "r"(a[3]), "r"(b[0]), "r"(b[1]));
}

__device__ __forceinline__ uint32_t ld32(const __half* p) { return *(const uint32_t*)p; }
__device__ __forceinline__ uint32_t h2u(__half2 h) { return *(uint32_t*)&h; }

// ===========================================================================
// Prep kernels: x -> fp16; W -> transposed fp16
// ===========================================================================
__global__ void __launch_bounds__(256)
xprep_kernel(const float* __restrict__ x) {
    int i = blockIdx.x * 256 + threadIdx.x;  // 8-float group
    float4 f0 = ((const float4*)x)[2 * i];
    float4 f1 = ((const float4*)x)[2 * i + 1];
    uint4 o;
    o.x = h2u(__floats2half2_rn(f0.x, f0.y));
    o.y = h2u(__floats2half2_rn(f0.z, f0.w));
    o.z = h2u(__floats2half2_rn(f1.x, f1.y));
    o.w = h2u(__floats2half2_rn(f1.z, f1.w));
    ((uint4*)g_xt)[i] = o;
}

__global__ void __launch_bounds__(256)
transpose_kernel(const float* __restrict__ W0, const float* __restrict__ W1,
                 const float* __restrict__ W2, const float* __restrict__ W3) {
    __shared__ float t[32][33];
    const float* W = (blockIdx.z == 0) ? W0 : (blockIdx.z == 1) ? W1 : (blockIdx.z == 2) ? W2 : W3;
    __half* Wt = g_wt + (size_t)blockIdx.z * D_MODEL * D_MODEL;
    int x = blockIdx.x * 32 + threadIdx.x;
    int y = blockIdx.y * 32 + threadIdx.y;
#pragma unroll
    for (int j = 0; j < 32; j += 8)
        t[threadIdx.y + j][threadIdx.x] = W[(size_t)(y + j) * D_MODEL + x];
    __syncthreads();
    int x2 = blockIdx.y * 32 + threadIdx.x;
    int y2 = blockIdx.x * 32 + threadIdx.y;
#pragma unroll
    for (int j = 0; j < 32; j += 8)
        Wt[(size_t)(y2 + j) * D_MODEL + x2] = __float2half_rn(t[threadIdx.x][threadIdx.y + j]);
}

// ===========================================================================
// fp16 mma GEMM: C[4096,1024] = A @ Wt^T + bias. 128x128 tile, BK=64 halves,
// 4 warps (2x2, warp tile 64x64), 2-stage cp.async. STRDH=72 halves/row.
// ===========================================================================
#define GBM 128
#define GBN 128
#define GBK 64
#define STRDH 72
#define STG_BYTES (128 * STRDH * 2)      // 18432
#define SM_TOTAL (4 * STG_BYTES)         // 73728

__device__ __forceinline__ size_t vt_idx(int row, int col) {
    // row = global token, col = h*64+d  -> [b*H+h][d][seq]
    return ((size_t)((row >> 11) * NUM_HEADS + (col >> 6)) * HEAD_DIM + (col & 63)) * SEQ
           + (row & (SEQ - 1));
}

__device__ __forceinline__ void issue_tile(uint32_t smb, int st,
                                           const __half* __restrict__ A,
                                           const __half* __restrict__ Bt,
                                           int row0, int col0, int k0, int tid) {
    uint32_t sA = smb + st * STG_BYTES;
    uint32_t sB = smb + 2 * STG_BYTES + st * STG_BYTES;
#pragma unroll
    for (int j = 0; j < 8; j++) {
        int idx = tid + j * 128;
        int m = idx >> 3, c8 = idx & 7;
        CP_ASYNC16(sA + m * (STRDH * 2) + c8 * 16,
                   A + (size_t)(row0 + m) * D_MODEL + k0 + c8 * 8);
        CP_ASYNC16(sB + m * (STRDH * 2) + c8 * 16,
                   Bt + (size_t)(col0 + m) * D_MODEL + k0 + c8 * 8);
    }
    CP_COMMIT();
}

// MODE: 0 = fp32 store (final out), 1 = fp16 store (q/k), 2 = fp16 V^T scatter
template <int MODE>
__device__ __forceinline__ void gemm_tile(const __half* __restrict__ A,
                                          const __half* __restrict__ Bt,
                                          const float* __restrict__ bias,
                                          void* __restrict__ Cv,
                                          char* sm, int row0, int col0, float scale) {
    const uint32_t smb = smem_to_u32(sm);
    const int tid = threadIdx.x;
    const int wid = tid >> 5;
    const int lane = tid & 31;
    const int gid = lane >> 2;
    const int tig = lane & 3;
    const int wm = wid >> 1;
    const int wn = wid & 1;

    float c[4][8][4];
#pragma unroll
    for (int mf = 0; mf < 4; mf++)
#pragma unroll
        for (int nf = 0; nf < 8; nf++)
#pragma unroll
            for (int i = 0; i < 4; i++) c[mf][nf][i] = 0.f;

    issue_tile(smb, 0, A, Bt, row0, col0, 0, tid);

    const int NT = D_MODEL / GBK;  // 16
    for (int it = 0; it < NT; it++) {
        if (it + 1 < NT) { issue_tile(smb, (it + 1) & 1, A, Bt, row0, col0, (it + 1) * GBK, tid); CP_WAIT1(); }
        else CP_WAIT0();
        __syncthreads();

        const int st = it & 1;
        const __half* As = (const __half*)(sm + st * STG_BYTES);
        const __half* Bs = (const __half*)(sm + 2 * STG_BYTES + st * STG_BYTES);

#pragma unroll
        for (int ks = 0; ks < 4; ks++) {
            const int kb = ks * 16;
            uint32_t a[4][4], b[8][2];
#pragma unroll
            for (int mf = 0; mf < 4; mf++) {
                const __half* r0 = As + (wm * 64 + mf * 16 + gid) * STRDH + kb + tig * 2;
                a[mf][0] = ld32(r0);
                a[mf][1] = ld32(r0 + 8 * STRDH);
                a[mf][2] = ld32(r0 + 8);
                a[mf][3] = ld32(r0 + 8 * STRDH + 8);
            }
#pragma unroll
            for (int nf = 0; nf < 8; nf++) {
                const __half* rn = Bs + (wn * 64 + nf * 8 + gid) * STRDH + kb + tig * 2;
                b[nf][0] = ld32(rn);
                b[nf][1] = ld32(rn + 8);
            }
#pragma unroll
            for (int mf = 0; mf < 4; mf++)
#pragma unroll
                for (int nf = 0; nf < 8; nf++)
                    mma_f16(c[mf][nf], a[mf], b[nf]);
        }
        __syncthreads();
    }

    // bias hoisted: depends only on nf
    float bb0[8], bb1[8];
#pragma unroll
    for (int nf = 0; nf < 8; nf++) {
        int col = col0 + wn * 64 + nf * 8 + tig * 2;
        bb0[nf] = __ldg(bias + col);
        bb1[nf] = __ldg(bias + col + 1);
    }
#pragma unroll
    for (int mf = 0; mf < 4; mf++) {
        int row = row0 + wm * 64 + mf * 16 + gid;
#pragma unroll
        for (int nf = 0; nf < 8; nf++) {
            int col = col0 + wn * 64 + nf * 8 + tig * 2;
            float v0 = (c[mf][nf][0] + bb0[nf]) * scale;
            float v1 = (c[mf][nf][1] + bb1[nf]) * scale;
            float v2 = (c[mf][nf][2] + bb0[nf]) * scale;
            float v3 = (c[mf][nf][3] + bb1[nf]) * scale;
            if (MODE == 0) {
                float* C = (float*)Cv;
                *(float2*)(C + (size_t)row * D_MODEL + col) = make_float2(v0, v1);
                *(float2*)(C + (size_t)(row + 8) * D_MODEL + col) = make_float2(v2, v3);
            } else if (MODE == 1) {
                __half* C = (__half*)Cv;
                *(__half2*)(C + (size_t)row * D_MODEL + col) = __floats2half2_rn(v0, v1);
                *(__half2*)(C + (size_t)(row + 8) * D_MODEL + col) = __floats2half2_rn(v2, v3);
            } else {
                __half* C = (__half*)Cv;
                C[vt_idx(row, col)]         = __float2half_rn(v0);
                C[vt_idx(row, col + 1)]     = __float2half_rn(v1);
                C[vt_idx(row + 8, col)]     = __float2half_rn(v2);
                C[vt_idx(row + 8, col + 1)] = __float2half_rn(v3);
            }
        }
    }
}

__global__ void __launch_bounds__(128, 2)
qkv_tc_kernel(const float* __restrict__ bq, const float* __restrict__ bk,
              const float* __restrict__ bv) {
    extern __shared__ char sm[];
    if (blockIdx.z == 0)
        gemm_tile<1>(g_xt, g_wt, bq, g_q, sm, blockIdx.y * GBM, blockIdx.x * GBN, 0.125f);
    else if (blockIdx.z == 1)
        gemm_tile<1>(g_xt, g_wt + (size_t)D_MODEL * D_MODEL, bk, g_k, sm,
                     blockIdx.y * GBM, blockIdx.x * GBN, 1.f);
    else
        gemm_tile<2>(g_xt, g_wt + 2ul * D_MODEL * D_MODEL, bv, g_v, sm,
                     blockIdx.y * GBM, blockIdx.x * GBN, 1.f);
}

__global__ void __launch_bounds__(128, 2)
out_tc_kernel(const float* __restrict__ bo, float* __restrict__ out) {
    extern __shared__ char sm[];
    gemm_tile<0>(g_attn, g_wt + 3ul * D_MODEL * D_MODEL, bo, out, sm,
                 blockIdx.y * GBM, blockIdx.x * GBN, 1.f);
}

// ===========================================================================
// Windowed flash attention, fp16 mma, cp.async double-buffered K/V^T.
// 256 threads (8 warps), QB=128, KB=64 (one sync + one softmax per 64 keys).
// Fully-valid tiles skip masking. Ps (fp16) aliases Qs.
// ===========================================================================
#define AQB 128
#define AKB 64
#define QS_STRD 72   // halves
#define KS_STRD 72
#define VT_STRD 72
#define PS_STRD 72

#define ASM_QS 0
#define ASM_KS (AQB * QS_STRD * 2)                 // 18432 (Ps aliases: 128*72*2 = same)
#define KS_STG (AKB * KS_STRD * 2)                 // 9216
#define ASM_VT (ASM_KS + 2 * KS_STG)               // 36864
#define VT_STG (HEAD_DIM * VT_STRD * 2)            // 9216
#define ASM_TOTAL (ASM_VT + 2 * VT_STG)            // 55296

__global__ void __launch_bounds__(256, 2)
attn_mma_kernel() {
    extern __shared__ char asm_sm[];
    __half* Qs = (__half*)(asm_sm + ASM_QS);   // becomes Ps after Q-frag preload
    const uint32_t smb = smem_to_u32(asm_sm);

    const int tid = threadIdx.x;
    const int wid = tid >> 5;
    const int lane = tid & 31;
    const int gid = lane >> 2;
    const int tig = lane & 3;

    const int q0 = blockIdx.x * AQB;
    const int h = blockIdx.y;
    const int b = blockIdx.z;
    const size_t rowbase = (size_t)b * SEQ;
    const int hoff = h * HEAD_DIM;
    const int bh = b * NUM_HEADS + h;

    // Load Q tile (128 x 64 halves), 16B chunks
    for (int i = tid; i < AQB * 8; i += 256) {
        int r = i >> 3, c8 = i & 7;
        uint4 v4 = *(const uint4*)(g_q + (rowbase + q0 + r) * D_MODEL + hoff + c8 * 8);
        *(uint4*)(Qs + r * QS_STRD + c8 * 8) = v4;
    }
    __syncthreads();

    // Preload Q fragments: 4 k-steps of k16
    uint32_t qa[4][4];
    {
        const __half* q0p = Qs + (wid * 16 + gid) * QS_STRD + tig * 2;
        const __half* q1p = q0p + 8 * QS_STRD;
#pragma unroll
        for (int ks = 0; ks < 4; ks++) {
            qa[ks][0] = ld32(q0p + ks * 16);
            qa[ks][1] = ld32(q1p + ks * 16);
            qa[ks][2] = ld32(q0p + ks * 16 + 8);
            qa[ks][3] = ld32(q1p + ks * 16 + 8);
        }
    }
    __syncthreads();

    float oc[8][4];
#pragma unroll
    for (int nf = 0; nf < 8; nf++)
#pragma unroll
        for (int i = 0; i < 4; i++) oc[nf][i] = 0.f;

    float m0 = -1e30f, m1 = -1e30f, l0 = 0.f, l1 = 0.f;
    const int r0w = q0 + wid * 16;        // warp's first q-row
    const int gi0 = r0w + gid;
    const int gi1 = gi0 + 8;
    const int wlo = r0w - WINDOW;         // smallest valid key for warp
    const int whi = r0w + 15;             // largest valid key for warp

    int kstart = q0 - WINDOW;
    if (kstart < 0) kstart = 0;
    const int NT = (q0 + AQB - kstart) / AKB;  // 2, 4, or 6

    // K tile: 64 rows x 8 chunks; V^T tile: 64 d-rows x 8 chunks. 2+2 per thread.
    auto load_kv = [&](int st, int k0) {
        uint32_t kdst = smb + ASM_KS + st * KS_STG;
        uint32_t vdst = smb + ASM_VT + st * VT_STG;
#pragma unroll
        for (int j = 0; j < 2; j++) {
            int idx = tid + j * 256;
            int r = idx >> 3, c8 = idx & 7;
            CP_ASYNC16(kdst + r * (KS_STRD * 2) + c8 * 16,
                       g_k + (rowbase + k0 + r) * D_MODEL + hoff + c8 * 8);
            CP_ASYNC16(vdst + r * (VT_STRD * 2) + c8 * 16,
                       g_v + ((size_t)bh * HEAD_DIM + r) * SEQ + k0 + c8 * 8);
        }
        CP_COMMIT();
    };

    load_kv(0, kstart);
    const int o2 = tig * 2;

    for (int it = 0; it < NT; it++) {
        if (it + 1 < NT) { load_kv((it + 1) & 1, kstart + (it + 1) * AKB); CP_WAIT1(); }
        else CP_WAIT0();
        __syncthreads();

        const int k0 = kstart + it * AKB;
        const int st = it & 1;
        const __half* Ks = (const __half*)(asm_sm + ASM_KS + st * KS_STG);
        const __half* Vt = (const __half*)(asm_sm + ASM_VT + st * VT_STG);

        if (!(k0 + AKB - 1 < wlo || k0 > whi)) {
            const bool fully_valid = (k0 + AKB - 1 <= r0w) && (k0 >= r0w + 15 - WINDOW);

            // S = Q @ K^T (16 x 64), 4 k16 steps, 8 key-frags
            float sc[8][4];
#pragma unroll
            for (int nf = 0; nf < 8; nf++)
#pragma unroll
                for (int i = 0; i < 4; i++) sc[nf][i] = 0.f;
#pragma unroll
            for (int ks = 0; ks < 4; ks++) {
                int kb = ks * 16;
                uint32_t bb[8][2];
#pragma unroll
                for (int nf = 0; nf < 8; nf++) {
                    const __half* kp = Ks + (nf * 8 + gid) * KS_STRD + kb + o2;
                    bb[nf][0] = ld32(kp);
                    bb[nf][1] = ld32(kp + 8);
                }
#pragma unroll
                for (int nf = 0; nf < 8; nf++) mma_f16(sc[nf], qa[ks], bb[nf]);
            }

            // Mask (partial tiles only) + single softmax update per 64 keys
            float tmax0 = -1e30f, tmax1 = -1e30f;
            if (!fully_valid) {
#pragma unroll
                for (int nf = 0; nf < 8; nf++) {
                    int col = k0 + nf * 8 + o2;
#pragma unroll
                    for (int e = 0; e < 2; e++) {
                        int gj = col + e;
                        if ((gj > gi0) || (gj < gi0 - WINDOW)) sc[nf][e] = -1e30f;
                        if ((gj > gi1) || (gj < gi1 - WINDOW)) sc[nf][e + 2] = -1e30f;
                    }
                }
            }
#pragma unroll
            for (int nf = 0; nf < 8; nf++) {
                tmax0 = fmaxf(tmax0, fmaxf(sc[nf][0], sc[nf][1]));
                tmax1 = fmaxf(tmax1, fmaxf(sc[nf][2], sc[nf][3]));
            }
            tmax0 = fmaxf(tmax0, __shfl_xor_sync(0xffffffffu, tmax0, 1));
            tmax0 = fmaxf(tmax0, __shfl_xor_sync(0xffffffffu, tmax0, 2));
            tmax1 = fmaxf(tmax1, __shfl_xor_sync(0xffffffffu, tmax1, 1));
            tmax1 = fmaxf(tmax1, __shfl_xor_sync(0xffffffffu, tmax1, 2));

            float mn0 = fmaxf(m0, tmax0), mn1 = fmaxf(m1, tmax1);
            float corr0 = __expf(m0 - mn0), corr1 = __expf(m1 - mn1);

            float ls0 = 0.f, ls1 = 0.f;
            __half* p0 = (__half*)asm_sm + (wid * 16 + gid) * PS_STRD;
            __half* p1 = p0 + 8 * PS_STRD;
#pragma unroll
            for (int nf = 0; nf < 8; nf++) {
                float pe0 = __expf(sc[nf][0] - mn0);
                float pe1 = __expf(sc[nf][1] - mn0);
                float pe2 = __expf(sc[nf][2] - mn1);
                float pe3 = __expf(sc[nf][3] - mn1);
                ls0 += pe0 + pe1;
                ls1 += pe2 + pe3;
                *(__half2*)(p0 + nf * 8 + o2) = __floats2half2_rn(pe0, pe1);
                *(__half2*)(p1 + nf * 8 + o2) = __floats2half2_rn(pe2, pe3);
            }
            ls0 += __shfl_xor_sync(0xffffffffu, ls0, 1);
            ls0 += __shfl_xor_sync(0xffffffffu, ls0, 2);
            ls1 += __shfl_xor_sync(0xffffffffu, ls1, 1);
            ls1 += __shfl_xor_sync(0xffffffffu, ls1, 2);

            l0 = l0 * corr0 + ls0;
            l1 = l1 * corr1 + ls1;
            m0 = mn0; m1 = mn1;
#pragma unroll
            for (int nf = 0; nf < 8; nf++) {
                oc[nf][0] *= corr0; oc[nf][1] *= corr0;
                oc[nf][2] *= corr1; oc[nf][3] *= corr1;
            }
            __syncwarp();

            // O += P @ V  (4 k16 steps over 64 keys)
#pragma unroll
            for (int ks2 = 0; ks2 < 4; ks2++) {
                int kb = ks2 * 16;
                uint32_t pa[4];
                pa[0] = ld32(p0 + kb + o2);
                pa[1] = ld32(p1 + kb + o2);
                pa[2] = ld32(p0 + kb + o2 + 8);
                pa[3] = ld32(p1 + kb + o2 + 8);
#pragma unroll
                for (int nf = 0; nf < 8; nf++) {
                    const __half* vp = Vt + (nf * 8 + gid) * VT_STRD + kb + o2;
                    uint32_t bb2[2];
                    bb2[0] = ld32(vp);
                    bb2[1] = ld32(vp + 8);
                    mma_f16(oc[nf], pa, bb2);
                }
            }
            __syncwarp();
        }
        __syncthreads();
    }

    // Epilogue: divide by l, store fp16 for the out-proj GEMM
    float inv0 = 1.f / l0, inv1 = 1.f / l1;
    __half* out0 = g_attn + (rowbase + gi0) * D_MODEL + hoff;
    __half* out1 = g_attn + (rowbase + gi1) * D_MODEL + hoff;
#pragma unroll
    for (int nf = 0; nf < 8; nf++) {
        *(__half2*)(out0 + nf * 8 + o2) = __floats2half2_rn(oc[nf][0] * inv0, oc[nf][1] * inv0);
        *(__half2*)(out1 + nf * 8 + o2) = __floats2half2_rn(oc[nf][2] * inv1, oc[nf][3] * inv1);
    }
}

// ---------------------------------------------------------------------------
extern "C" void kernel_launch(void* const* d_in, const int* in_sizes, int n_in,
                              void* d_out, int out_size) {
    const float* x  = (const float*)d_in[0];
    const float* Wq = (const float*)d_in[1];
    const float* bq = (const float*)d_in[2];
    const float* Wk = (const float*)d_in[3];
    const float* bk = (const float*)d_in[4];
    const float* Wv = (const float*)d_in[5];
    const float* bv = (const float*)d_in[6];
    const float* Wo = (const float*)d_in[7];
    const float* bo = (const float*)d_in[8];
    float* out = (float*)d_out;

    cudaFuncSetAttribute(qkv_tc_kernel, cudaFuncAttributeMaxDynamicSharedMemorySize, SM_TOTAL);
    cudaFuncSetAttribute(out_tc_kernel, cudaFuncAttributeMaxDynamicSharedMemorySize, SM_TOTAL);
    cudaFuncSetAttribute(attn_mma_kernel, cudaFuncAttributeMaxDynamicSharedMemorySize, ASM_TOTAL);

    xprep_kernel<<<MTOT * D_MODEL / 8 / 256, 256>>>(x);
    transpose_kernel<<<dim3(32, 32, 4), dim3(32, 8)>>>(Wq, Wk, Wv, Wo);

    dim3 gQKV(D_MODEL / GBN, MTOT / GBM, 3);  // (8, 32, 3)
    qkv_tc_kernel<<<gQKV, 128, SM_TOTAL>>>(bq, bk, bv);

    dim3 gAttn(SEQ / AQB, NUM_HEADS, BATCH);  // (16, 16, 2)
    attn_mma_kernel<<<gAttn, 256, ASM_TOTAL>>>();

    dim3 gOut(D_MODEL / GBN, MTOT / GBM);     // (8, 32)
    out_tc_kernel<<<gOut, 128, SM_TOTAL>>>(bo, out);
}